// round 5
// baseline (speedup 1.0000x reference)
#include <cuda_runtime.h>
#include <math.h>
#include <stdint.h>

#define Bq    32
#define Lq    512
#define Dq    768
#define HIDq  192
#define DIq   1536
#define DSq   16
#define DTRq  48
#define Nq    (Bq*Lq)        // 16384
#define EPSq  1e-5f

// ---------------- scratch (static device allocations; no cudaMalloc) ----------------
__device__ __align__(256) float g_h0  [Nq*HIDq];
__device__ __align__(256) float g_tmpH[Nq*HIDq];
__device__ __align__(256) float g_h2  [Nq*HIDq];
__device__ __align__(256) float g_e   [Nq*Dq];
__device__ __align__(256) float g_x1  [Nq*Dq];
__device__ __align__(256) float g_xn  [Nq*Dq];
__device__ __align__(256) float g_xz  [Nq*2*DIq];     // 3072 wide: xm | z
__device__ __align__(256) float g_xm2 [Nq*DIq];
__device__ __align__(256) float g_dbc [Nq*80];        // dt(48) | B(16) | C(16)
__device__ __align__(256) float g_del [Nq*DIq];
__device__ __align__(256) float g_y   [Nq*DIq];
__device__ __align__(256) float g_gl  [Nq*Dq];
__device__ __align__(256) float g_xf  [Nq*Dq];
__device__ __align__(256) float g_rm  [Nq];
__device__ __align__(256) float g_rs  [Nq];
__device__ __align__(256) float g_fid [Bq*Dq];
// stats region (zeroed once per call):
// rowsum[16384] | rowsq[16384] | sum1[192] sq1[192] sum2[192] sq2[192] | sum3[768] sq3[768]
#define ST_ROWSUM 0
#define ST_ROWSQ  16384
#define ST_SUM1   32768
#define ST_SQ1    (ST_SUM1+192)
#define ST_SUM2   (ST_SQ1+192)
#define ST_SQ2    (ST_SUM2+192)
#define ST_SUM3   (ST_SQ2+192)
#define ST_SQ3    (ST_SUM3+768)
#define ST_TOTAL  (ST_SQ3+768)
__device__ __align__(256) float g_stats[ST_TOTAL];

// ================= TF32 mma.sync GEMM =================
// C[M,Nc] = A[M,K](lda) @ W[Nc,K]^T.  BM=128, BN=128, BK=32.
// 8 warps = 4(M) x 2(N); warp tile 32x64; mma.m16n8k8.tf32.
// Epilogue modes: 0 = plain store; 1 = softplus(v + p0[c]);
//                 2 = combine: xf = p1[idx] + v*sigmoid(p2[idx]+p3[c]) + p0[idx],
//                     plus atomic per-row sum/sq of xf into paux0/paux1.
#define SA 36

__device__ __forceinline__ uint32_t f2tf(float f) {
    uint32_t u;
    asm("cvt.rna.tf32.f32 %0, %1;" : "=r"(u) : "f"(f));
    return u;
}

__device__ __forceinline__ void mma_tf32(float* d, const uint32_t* a, const uint32_t* b) {
    asm volatile(
        "mma.sync.aligned.m16n8k8.row.col.f32.tf32.tf32.f32 "
        "{%0,%1,%2,%3}, {%4,%5,%6,%7}, {%8,%9}, {%0,%1,%2,%3};"
        : "+f"(d[0]), "+f"(d[1]), "+f"(d[2]), "+f"(d[3])
        : "r"(a[0]), "r"(a[1]), "r"(a[2]), "r"(a[3]), "r"(b[0]), "r"(b[1]));
}

__global__ void __launch_bounds__(256) gemm_tc(
    const float* __restrict__ A, int lda,
    const float* __restrict__ W,
    float* __restrict__ C, int Nc, int K,
    int mode,
    const float* __restrict__ p0, const float* __restrict__ p1,
    const float* __restrict__ p2, const float* __restrict__ p3,
    float* __restrict__ paux0, float* __restrict__ paux1)
{
    __shared__ uint32_t As[128*SA];
    __shared__ uint32_t Bs[128*SA];

    const int bm = blockIdx.y * 128;
    const int bn = blockIdx.x * 128;
    const int t  = threadIdx.x;
    const int wid  = t >> 5;
    const int lane = t & 31;
    const int qr = lane >> 2;   // 0..7
    const int qc = lane & 3;    // 0..3
    const int warp_m = wid & 3;
    const int warp_n = wid >> 2;

    float acc[2][8][4];
    #pragma unroll
    for (int mt = 0; mt < 2; mt++)
        #pragma unroll
        for (int nt = 0; nt < 8; nt++)
            #pragma unroll
            for (int q = 0; q < 4; q++) acc[mt][nt][q] = 0.f;

    const int NC = (K + 31) / 32;

    float4 aReg[4], bReg[4];
    const float4 z4 = make_float4(0.f, 0.f, 0.f, 0.f);

    // prologue: stage chunk 0
    {
        #pragma unroll
        for (int i = 0; i < 4; i++) {
            int idx = t + i*256;
            int r = idx >> 3;
            int c4 = (idx & 7) * 4;
            aReg[i] = (c4 < K) ? *(const float4*)&A[(size_t)(bm + r)*lda + c4] : z4;
            int j = bn + r;
            bReg[i] = (j < Nc && c4 < K) ? *(const float4*)&W[(size_t)j*K + c4] : z4;
        }
    }

    for (int ch = 0; ch < NC; ch++) {
        __syncthreads();
        #pragma unroll
        for (int i = 0; i < 4; i++) {
            int idx = t + i*256;
            int r = idx >> 3;
            int c4 = (idx & 7) * 4;
            uint4 ua = make_uint4(f2tf(aReg[i].x), f2tf(aReg[i].y), f2tf(aReg[i].z), f2tf(aReg[i].w));
            uint4 ub = make_uint4(f2tf(bReg[i].x), f2tf(bReg[i].y), f2tf(bReg[i].z), f2tf(bReg[i].w));
            *(uint4*)&As[r*SA + c4] = ua;
            *(uint4*)&Bs[r*SA + c4] = ub;
        }
        __syncthreads();

        if (ch + 1 < NC) {
            const int k0 = (ch + 1) * 32;
            #pragma unroll
            for (int i = 0; i < 4; i++) {
                int idx = t + i*256;
                int r = idx >> 3;
                int c4 = (idx & 7) * 4;
                aReg[i] = (k0 + c4 < K) ? *(const float4*)&A[(size_t)(bm + r)*lda + k0 + c4] : z4;
                int j = bn + r;
                bReg[i] = (j < Nc && k0 + c4 < K) ? *(const float4*)&W[(size_t)j*K + k0 + c4] : z4;
            }
        }

        #pragma unroll
        for (int ks = 0; ks < 4; ks++) {
            const int k0 = ks * 8;
            uint32_t afr[2][4];
            #pragma unroll
            for (int mt = 0; mt < 2; mt++) {
                int r0 = warp_m*32 + mt*16 + qr;
                afr[mt][0] = As[r0*SA + k0 + qc];
                afr[mt][1] = As[(r0+8)*SA + k0 + qc];
                afr[mt][2] = As[r0*SA + k0 + qc + 4];
                afr[mt][3] = As[(r0+8)*SA + k0 + qc + 4];
            }
            uint32_t bfr[8][2];
            #pragma unroll
            for (int nt = 0; nt < 8; nt++) {
                int n = warp_n*64 + nt*8 + qr;
                bfr[nt][0] = Bs[n*SA + k0 + qc];
                bfr[nt][1] = Bs[n*SA + k0 + qc + 4];
            }
            #pragma unroll
            for (int mt = 0; mt < 2; mt++)
                #pragma unroll
                for (int nt = 0; nt < 8; nt++)
                    mma_tf32(acc[mt][nt], afr[mt], bfr[nt]);
        }
    }

    // ---------------- epilogue ----------------
    if (mode == 0) {
        #pragma unroll
        for (int mt = 0; mt < 2; mt++) {
            int r0 = bm + warp_m*32 + mt*16 + qr;
            #pragma unroll
            for (int nt = 0; nt < 8; nt++) {
                int c = bn + warp_n*64 + nt*8 + qc*2;
                if (c < Nc) {
                    *(float2*)&C[(size_t)r0*Nc + c]     = make_float2(acc[mt][nt][0], acc[mt][nt][1]);
                    *(float2*)&C[(size_t)(r0+8)*Nc + c] = make_float2(acc[mt][nt][2], acc[mt][nt][3]);
                }
            }
        }
    } else if (mode == 1) {
        // delta = softplus(v + bias[c])
        #pragma unroll
        for (int mt = 0; mt < 2; mt++) {
            int r0 = bm + warp_m*32 + mt*16 + qr;
            #pragma unroll
            for (int nt = 0; nt < 8; nt++) {
                int c = bn + warp_n*64 + nt*8 + qc*2;
                if (c < Nc) {
                    float b0 = p0[c], b1 = p0[c+1];
                    float v;
                    v = acc[mt][nt][0] + b0; v = (v > 20.f) ? v : log1pf(__expf(v));
                    C[(size_t)r0*Nc + c] = v;
                    v = acc[mt][nt][1] + b1; v = (v > 20.f) ? v : log1pf(__expf(v));
                    C[(size_t)r0*Nc + c + 1] = v;
                    v = acc[mt][nt][2] + b0; v = (v > 20.f) ? v : log1pf(__expf(v));
                    C[(size_t)(r0+8)*Nc + c] = v;
                    v = acc[mt][nt][3] + b1; v = (v > 20.f) ? v : log1pf(__expf(v));
                    C[(size_t)(r0+8)*Nc + c + 1] = v;
                }
            }
        }
    } else {
        // combine: xf = x1 + v*sigmoid(gl+gb) + x ; accumulate row sums
        #pragma unroll
        for (int mt = 0; mt < 2; mt++) {
            int rlo = bm + warp_m*32 + mt*16 + qr;
            int rhi = rlo + 8;
            float s0 = 0.f, ss0 = 0.f, s1 = 0.f, ss1 = 0.f;
            #pragma unroll
            for (int nt = 0; nt < 8; nt++) {
                int c = bn + warp_n*64 + nt*8 + qc*2;
                if (c < Nc) {
                    #pragma unroll
                    for (int h = 0; h < 2; h++) {
                        size_t i0 = (size_t)rlo*Nc + c + h;
                        float gate = 1.f / (1.f + __expf(-(p2[i0] + p3[c+h])));
                        float xfv = p1[i0] + acc[mt][nt][h]*gate + p0[i0];
                        C[i0] = xfv; s0 += xfv; ss0 += xfv*xfv;
                        size_t i1 = (size_t)rhi*Nc + c + h;
                        gate = 1.f / (1.f + __expf(-(p2[i1] + p3[c+h])));
                        xfv = p1[i1] + acc[mt][nt][h+2]*gate + p0[i1];
                        C[i1] = xfv; s1 += xfv; ss1 += xfv*xfv;
                    }
                }
            }
            atomicAdd(&paux0[rlo], s0); atomicAdd(&paux1[rlo], ss0);
            atomicAdd(&paux0[rhi], s1); atomicAdd(&paux1[rhi], ss1);
        }
    }
}

// ---------------- BatchNorm stats over all rows, per channel ----------------
__global__ void bn_stats(const float* __restrict__ X, int M, int C,
                         float* __restrict__ sum, float* __restrict__ sq)
{
    int c = blockIdx.y * blockDim.x + threadIdx.x;
    if (c >= C) return;
    int rows = M / gridDim.x;
    int r0 = blockIdx.x * rows;
    float s = 0.f, ss = 0.f;
    for (int r = r0; r < r0 + rows; r++) {
        float v = X[(size_t)r*C + c];
        s += v; ss += v*v;
    }
    atomicAdd(&sum[c], s);
    atomicAdd(&sq[c],  ss);
}

__global__ void bn_silu(const float* __restrict__ X, float* __restrict__ Y,
                        const float* __restrict__ sum, const float* __restrict__ sq,
                        const float* __restrict__ g, const float* __restrict__ b,
                        int M, int C)
{
    int idx = blockIdx.x * blockDim.x + threadIdx.x;
    if (idx >= M*C) return;
    int c = idx % C;
    float mean = sum[c] / (float)M;
    float var  = sq[c] / (float)M - mean*mean;
    float v = (X[idx] - mean) * rsqrtf(var + EPSq) * g[c] + b[c];
    Y[idx] = v / (1.f + __expf(-v));
}

// ---------------- dwconv5 fused with input-side bn+silu ----------------
// Y[l,c] = sum_k w[c,k] * silu(bn1(X[l-2+k, c]))
__global__ void dwconv_fused(const float* __restrict__ X, const float* __restrict__ w,
                             const float* __restrict__ sum, const float* __restrict__ sq,
                             const float* __restrict__ g, const float* __restrict__ b,
                             float* __restrict__ Y)
{
    int idx = blockIdx.x * blockDim.x + threadIdx.x;
    if (idx >= Nq*HIDq) return;
    int c  = idx % HIDq;
    int l  = (idx / HIDq) % Lq;
    int bb = idx / (HIDq*Lq);
    float mean = sum[c] / (float)Nq;
    float var  = sq[c] / (float)Nq - mean*mean;
    float ga = rsqrtf(var + EPSq) * g[c];
    float be = b[c] - mean * ga;
    const float* xb = X + (size_t)bb*Lq*HIDq;
    float acc = 0.f;
    #pragma unroll
    for (int k = 0; k < 5; k++) {
        int ls = l - 2 + k;
        if (ls >= 0 && ls < Lq) {
            float v = xb[(size_t)ls*HIDq + c] * ga + be;
            acc += (v / (1.f + __expf(-v))) * w[c*5 + k];
        }
    }
    Y[idx] = acc;
}

// ---------------- bn_add + LN stats + LN apply, fused (block per row) ----------------
// x1 = x + bn3(e); xn = LN(x1)*g+b; writes rm/rs for attr_max.
__global__ void __launch_bounds__(256) bn_add_ln(
    const float* __restrict__ E, const float* __restrict__ X,
    const float* __restrict__ sum3, const float* __restrict__ sq3,
    const float* __restrict__ exg, const float* __restrict__ exb,
    const float* __restrict__ lng, const float* __restrict__ lnb,
    float* __restrict__ X1, float* __restrict__ XN,
    float* __restrict__ rm, float* __restrict__ rs)
{
    const int row = blockIdx.x;
    const int tid = threadIdx.x;
    float vloc[3];
    float s = 0.f, ss = 0.f;
    #pragma unroll
    for (int j = 0; j < 3; j++) {
        int c = tid + j*256;
        float mean = sum3[c] / (float)Nq;
        float var  = sq3[c] / (float)Nq - mean*mean;
        float ga = rsqrtf(var + EPSq) * exg[c];
        float be = exb[c] - mean*ga;
        float v = X[(size_t)row*Dq + c] + E[(size_t)row*Dq + c]*ga + be;
        vloc[j] = v;
        s += v; ss += v*v;
    }
    __shared__ float sh1[8], sh2[8], bcast[2];
    for (int o = 16; o; o >>= 1) {
        s  += __shfl_down_sync(0xffffffffu, s, o);
        ss += __shfl_down_sync(0xffffffffu, ss, o);
    }
    int lane = tid & 31, warp = tid >> 5;
    if (lane == 0) { sh1[warp] = s; sh2[warp] = ss; }
    __syncthreads();
    if (tid == 0) {
        s = 0.f; ss = 0.f;
        #pragma unroll
        for (int wv = 0; wv < 8; wv++) { s += sh1[wv]; ss += sh2[wv]; }
        float m = s / (float)Dq;
        float v = ss / (float)Dq - m*m;
        float r = rsqrtf(v + EPSq);
        bcast[0] = m; bcast[1] = r;
        rm[row] = m; rs[row] = r;
    }
    __syncthreads();
    float m = bcast[0], r = bcast[1];
    #pragma unroll
    for (int j = 0; j < 3; j++) {
        int c = tid + j*256;
        X1[(size_t)row*Dq + c] = vloc[j];
        XN[(size_t)row*Dq + c] = (vloc[j] - m) * r * lng[c] + lnb[c];
    }
}

// ---------------- causal depthwise conv K=4 + bias + silu ----------------
__global__ void conv_causal_silu(const float* __restrict__ XZ, const float* __restrict__ w,
                                 const float* __restrict__ bias, float* __restrict__ Y)
{
    int idx = blockIdx.x * blockDim.x + threadIdx.x;
    if (idx >= Nq*DIq) return;
    int c  = idx % DIq;
    int l  = (idx / DIq) % Lq;
    int bb = idx / (DIq*Lq);
    float acc = bias[c];
    #pragma unroll
    for (int k = 0; k < 4; k++) {
        int ls = l - 3 + k;
        if (ls >= 0) acc += XZ[(size_t)(bb*Lq + ls)*(2*DIq) + c] * w[c*4 + k];
    }
    Y[idx] = acc / (1.f + __expf(-acc));
}

// feat_attr[b,c] = max_l LN(x1)[b,l,c]
__global__ void attr_max(const float* __restrict__ X, const float* __restrict__ mean,
                         const float* __restrict__ rstd, const float* __restrict__ g,
                         const float* __restrict__ b, float* __restrict__ out)
{
    int c  = blockIdx.y * blockDim.x + threadIdx.x;
    int bb = blockIdx.x;
    float gm = g[c], gb = b[c];
    float mx = -3.4e38f;
    for (int l = 0; l < Lq; l++) {
        int row = bb*Lq + l;
        float v = (X[(size_t)row*Dq + c] - mean[row]) * rstd[row] * gm + gb;
        mx = fmaxf(mx, v);
    }
    out[bb*Dq + c] = mx;
}

// ---------------- selective scan (prefetched) ----------------
__global__ void __launch_bounds__(256) scan_k(
    const float* __restrict__ delta, const float* __restrict__ u,
    const float* __restrict__ dbc,   const float* __restrict__ xz,
    const float* __restrict__ A_log, const float* __restrict__ Dp,
    float* __restrict__ y)
{
    __shared__ float Bs[128][DSq];
    __shared__ float Cs[128][DSq];
    const int bb = blockIdx.y;
    const int d  = blockIdx.x * 256 + threadIdx.x;

    float A[DSq], h[DSq];
    #pragma unroll
    for (int s = 0; s < DSq; s++) { A[s] = -expf(A_log[d*DSq + s]); h[s] = 0.f; }
    const float dp = Dp[d];

    for (int c0 = 0; c0 < Lq; c0 += 128) {
        for (int i = threadIdx.x; i < 128*DSq; i += 256) {
            int l = i >> 4, s = i & 15;
            size_t row = (size_t)(bb*Lq + c0 + l);
            Bs[l][s] = dbc[row*80 + DTRq + s];
            Cs[l][s] = dbc[row*80 + DTRq + DSq + s];
        }
        __syncthreads();
        size_t row0 = (size_t)(bb*Lq + c0);
        float dv = delta[row0*DIq + d];
        float uv = u[row0*DIq + d];
        float zv = xz[row0*(2*DIq) + DIq + d];
        for (int l = 0; l < 128; l++) {
            float nd = 0.f, nu = 0.f, nz = 0.f;
            if (l < 127) {
                size_t rn = row0 + l + 1;
                nd = delta[rn*DIq + d];
                nu = u[rn*DIq + d];
                nz = xz[rn*(2*DIq) + DIq + d];
            }
            float du = dv * uv;
            float acc = 0.f;
            #pragma unroll
            for (int s = 0; s < DSq; s++) {
                h[s] = h[s] * __expf(dv * A[s]) + du * Bs[l][s];
                acc  = fmaf(h[s], Cs[l][s], acc);
            }
            float sz = zv / (1.f + __expf(-zv));
            y[(row0 + l)*DIq + d] = (acc + uv*dp) * sz;
            dv = nd; uv = nu; zv = nz;
        }
        __syncthreads();
    }
}

// feat_id[b,c] = mean_l LN(xf)[b,l,c], using fused row sums
__global__ void feat_id_k(const float* __restrict__ X, const float* __restrict__ rowsum,
                          const float* __restrict__ rowsq, const float* __restrict__ g,
                          const float* __restrict__ b, float* __restrict__ fid,
                          float* __restrict__ out)
{
    int c  = blockIdx.y * blockDim.x + threadIdx.x;
    int bb = blockIdx.x;
    float gm = g[c], gb = b[c];
    float s = 0.f;
    for (int l = 0; l < Lq; l++) {
        int row = bb*Lq + l;
        float m = rowsum[row] / (float)Dq;
        float var = rowsq[row] / (float)Dq - m*m;
        float r = rsqrtf(var + EPSq);
        s += (X[(size_t)row*Dq + c] - m) * r * gm + gb;
    }
    float v = s / (float)Lq;
    fid[bb*Dq + c] = v;
    out[bb*Dq + c] = v;
}

__global__ void feat_bn(const float* __restrict__ fid, const float* __restrict__ g,
                        const float* __restrict__ b, float* __restrict__ out)
{
    int c = blockIdx.x * blockDim.x + threadIdx.x;
    if (c >= Dq) return;
    float s = 0.f, ss = 0.f;
    for (int bb = 0; bb < Bq; bb++) {
        float v = fid[bb*Dq + c]; s += v; ss += v*v;
    }
    float m = s / (float)Bq;
    float var = ss / (float)Bq - m*m;
    float rs = rsqrtf(var + EPSq);
    for (int bb = 0; bb < Bq; bb++)
        out[bb*Dq + c] = (fid[bb*Dq + c] - m) * rs * g[c] + b[c];
}

// ---------------- host ----------------
#define GETSYM(p, s) { void* _t; cudaGetSymbolAddress(&_t, s); p = (float*)_t; }

static inline void launch_gemm(const float* A, int lda, const float* W, float* C,
                               int Nc, int K, int mode = 0,
                               const float* p0 = 0, const float* p1 = 0,
                               const float* p2 = 0, const float* p3 = 0,
                               float* paux0 = 0, float* paux1 = 0)
{
    dim3 grid((Nc + 127) / 128, Nq / 128);
    gemm_tc<<<grid, 256>>>(A, lda, W, C, Nc, K, mode, p0, p1, p2, p3, paux0, paux1);
}

extern "C" void kernel_launch(void* const* d_in, const int* in_sizes, int n_in,
                              void* d_out, int out_size)
{
    const float* x        = (const float*)d_in[0];
    const float* sq_w     = (const float*)d_in[1];
    const float* sq_bn_g  = (const float*)d_in[2];
    const float* sq_bn_b  = (const float*)d_in[3];
    const float* dw_w     = (const float*)d_in[4];
    const float* dw_bn_g  = (const float*)d_in[5];
    const float* dw_bn_b  = (const float*)d_in[6];
    const float* ex_w     = (const float*)d_in[7];
    const float* ex_bn_g  = (const float*)d_in[8];
    const float* ex_bn_b  = (const float*)d_in[9];
    const float* attr_g   = (const float*)d_in[10];
    const float* attr_b   = (const float*)d_in[11];
    const float* mnorm_g  = (const float*)d_in[12];
    const float* mnorm_b  = (const float*)d_in[13];
    const float* in_proj_w= (const float*)d_in[14];
    const float* conv_w   = (const float*)d_in[15];
    const float* conv_b   = (const float*)d_in[16];
    const float* xproj_w  = (const float*)d_in[17];
    const float* dtproj_w = (const float*)d_in[18];
    const float* dtproj_b = (const float*)d_in[19];
    const float* A_log    = (const float*)d_in[20];
    const float* D_param  = (const float*)d_in[21];
    const float* out_proj_w = (const float*)d_in[22];
    const float* gate_w   = (const float*)d_in[23];
    const float* gate_b   = (const float*)d_in[24];
    const float* idn_g    = (const float*)d_in[25];
    const float* idn_b    = (const float*)d_in[26];
    const float* idbn_g   = (const float*)d_in[27];
    const float* idbn_b   = (const float*)d_in[28];
    float* out = (float*)d_out;

    float *h0,*tmpH,*h2,*e,*x1,*xn,*xz,*xm2,*dbc,*del,*y,*gl,*xf;
    float *rm,*rs,*fid,*stats;
    GETSYM(h0, g_h0);   GETSYM(tmpH, g_tmpH); GETSYM(h2, g_h2);
    GETSYM(e, g_e);     GETSYM(x1, g_x1);     GETSYM(xn, g_xn);
    GETSYM(xz, g_xz);   GETSYM(xm2, g_xm2);   GETSYM(dbc, g_dbc);
    GETSYM(del, g_del); GETSYM(y, g_y);       GETSYM(gl, g_gl);
    GETSYM(xf, g_xf);   GETSYM(rm, g_rm);     GETSYM(rs, g_rs);
    GETSYM(fid, g_fid); GETSYM(stats, g_stats);

    float* rowsum = stats + ST_ROWSUM;
    float* rowsq  = stats + ST_ROWSQ;
    float* sum1   = stats + ST_SUM1;
    float* sq1    = stats + ST_SQ1;
    float* sum2   = stats + ST_SUM2;
    float* sq2    = stats + ST_SQ2;
    float* sum3   = stats + ST_SUM3;
    float* sq3    = stats + ST_SQ3;

    const int T = 256;
    dim3 gHID((Nq*HIDq + T-1)/T), gDI((Nq*DIq + T-1)/T);

    // 0) zero stats
    cudaMemsetAsync(stats, 0, ST_TOTAL*sizeof(float));

    // 1) squeeze GEMM + bn stats
    launch_gemm(x, Dq, sq_w, h0, HIDq, Dq);
    bn_stats<<<dim3(32,1), T>>>(h0, Nq, HIDq, sum1, sq1);

    // 2) dwconv(silu(bn1(.))) + bn stats + bn_silu -> h2
    dwconv_fused<<<gHID, T>>>(h0, dw_w, sum1, sq1, sq_bn_g, sq_bn_b, tmpH);
    bn_stats<<<dim3(32,1), T>>>(tmpH, Nq, HIDq, sum2, sq2);
    bn_silu<<<gHID, T>>>(tmpH, h2, sum2, sq2, dw_bn_g, dw_bn_b, Nq, HIDq);

    // 3) excite GEMM + bn stats; fused bn_add + LN -> x1, xn, rm, rs
    launch_gemm(h2, HIDq, ex_w, e, Dq, HIDq);
    bn_stats<<<dim3(32,3), T>>>(e, Nq, Dq, sum3, sq3);
    bn_add_ln<<<Nq, T>>>(e, x, sum3, sq3, ex_bn_g, ex_bn_b, mnorm_g, mnorm_b,
                         x1, xn, rm, rs);

    // 4) feat_attr
    attr_max<<<dim3(Bq,3), T>>>(x1, rm, rs, attr_g, attr_b, out);

    // 5) Mamba in_proj
    launch_gemm(xn, Dq, in_proj_w, xz, 2*DIq, Dq);

    // 6) causal conv + silu -> xm2
    conv_causal_silu<<<gDI, T>>>(xz, conv_w, conv_b, xm2);

    // 7) x_proj -> dbc ; dt_proj (+softplus epilogue) -> del
    launch_gemm(xm2, DIq, xproj_w, dbc, 80, DIq);
    launch_gemm(dbc, 80, dtproj_w, del, DIq, DTRq, 1, dtproj_b);

    // 8) selective scan (fused +u*D and *silu(z))
    scan_k<<<dim3(DIq/256, Bq), 256>>>(del, xm2, dbc, xz, A_log, D_param, y);

    // 9) gate GEMM; out_proj GEMM with fused combine + row-stat atomics
    launch_gemm(xn, Dq, gate_w, gl, Dq, Dq);
    launch_gemm(y, DIq, out_proj_w, xf, Dq, DIq, 2, x, x1, gl, gate_b, rowsum, rowsq);

    // 10) feat_id + feat_id_bn
    feat_id_k<<<dim3(Bq,3), T>>>(xf, rowsum, rowsq, idn_g, idn_b, fid, out + Bq*Dq);
    feat_bn<<<3, T>>>(fid, idbn_g, idbn_b, out + 2*Bq*Dq);
}

// round 6
// speedup vs baseline: 1.4858x; 1.4858x over previous
#include <cuda_runtime.h>
#include <math.h>
#include <stdint.h>

#define Bq    32
#define Lq    512
#define Dq    768
#define HIDq  192
#define DIq   1536
#define DSq   16
#define DTRq  48
#define Nq    (Bq*Lq)        // 16384
#define EPSq  1e-5f

// ---------------- scratch (static device allocations; no cudaMalloc) ----------------
__device__ __align__(256) float g_h0  [Nq*HIDq];
__device__ __align__(256) float g_tmpH[Nq*HIDq];
__device__ __align__(256) float g_h2  [Nq*HIDq];
__device__ __align__(256) float g_e   [Nq*Dq];
__device__ __align__(256) float g_x1  [Nq*Dq];
__device__ __align__(256) float g_xn  [Nq*Dq];
__device__ __align__(256) float g_xz  [Nq*2*DIq];     // 3072 wide: xm | z
__device__ __align__(256) float g_xm2 [Nq*DIq];
__device__ __align__(256) float g_dbc [Nq*80];        // dt(48) | B(16) | C(16)
__device__ __align__(256) float g_del [Nq*DIq];
__device__ __align__(256) float g_y   [Nq*DIq];
__device__ __align__(256) float g_gl  [Nq*Dq];
__device__ __align__(256) float g_xf  [Nq*Dq];
__device__ __align__(256) float g_rm  [Nq];
__device__ __align__(256) float g_rs  [Nq];
__device__ __align__(256) float g_fid [Bq*Dq];
// stats region (zeroed once per call)
#define ST_ROWSUM 0
#define ST_ROWSQ  16384
#define ST_SUM1   32768
#define ST_SQ1    (ST_SUM1+192)
#define ST_SUM2   (ST_SQ1+192)
#define ST_SQ2    (ST_SUM2+192)
#define ST_SUM3   (ST_SQ2+192)
#define ST_SQ3    (ST_SUM3+768)
#define ST_TOTAL  (ST_SQ3+768)
__device__ __align__(256) float g_stats[ST_TOTAL];

// ================= TF32 mma.sync GEMM (templated epilogue) =================
// C[M,Nc] = A[M,K](lda) @ W[Nc,K]^T.  BM=128, BN=128, BK=32.
// 8 warps = 4(M) x 2(N); warp tile 32x64; mma.m16n8k8.tf32.
// MODE 0: plain store. MODE 1: softplus(v + p0[c]). MODE 2: combine + row stats.
#define SA 36

__device__ __forceinline__ uint32_t f2tf(float f) {
    uint32_t u;
    asm("cvt.rna.tf32.f32 %0, %1;" : "=r"(u) : "f"(f));
    return u;
}

__device__ __forceinline__ void mma_tf32(float* d, const uint32_t* a, const uint32_t* b) {
    asm volatile(
        "mma.sync.aligned.m16n8k8.row.col.f32.tf32.tf32.f32 "
        "{%0,%1,%2,%3}, {%4,%5,%6,%7}, {%8,%9}, {%0,%1,%2,%3};"
        : "+f"(d[0]), "+f"(d[1]), "+f"(d[2]), "+f"(d[3])
        : "r"(a[0]), "r"(a[1]), "r"(a[2]), "r"(a[3]), "r"(b[0]), "r"(b[1]));
}

template<int MODE>
__global__ void __launch_bounds__(256) gemm_tc(
    const float* __restrict__ A, int lda,
    const float* __restrict__ W,
    float* __restrict__ C, int Nc, int K,
    const float* __restrict__ p0, const float* __restrict__ p1,
    const float* __restrict__ p2, const float* __restrict__ p3,
    float* __restrict__ paux0, float* __restrict__ paux1)
{
    __shared__ uint32_t As[128*SA];
    __shared__ uint32_t Bs[128*SA];

    const int bm = blockIdx.y * 128;
    const int bn = blockIdx.x * 128;
    const int t  = threadIdx.x;
    const int wid  = t >> 5;
    const int lane = t & 31;
    const int qr = lane >> 2;
    const int qc = lane & 3;
    const int warp_m = wid & 3;
    const int warp_n = wid >> 2;

    float acc[2][8][4];
    #pragma unroll
    for (int mt = 0; mt < 2; mt++)
        #pragma unroll
        for (int nt = 0; nt < 8; nt++)
            #pragma unroll
            for (int q = 0; q < 4; q++) acc[mt][nt][q] = 0.f;

    const int NC = (K + 31) / 32;

    float4 aReg[4], bReg[4];
    const float4 z4 = make_float4(0.f, 0.f, 0.f, 0.f);

    {
        #pragma unroll
        for (int i = 0; i < 4; i++) {
            int idx = t + i*256;
            int r = idx >> 3;
            int c4 = (idx & 7) * 4;
            aReg[i] = (c4 < K) ? *(const float4*)&A[(size_t)(bm + r)*lda + c4] : z4;
            int j = bn + r;
            bReg[i] = (j < Nc && c4 < K) ? *(const float4*)&W[(size_t)j*K + c4] : z4;
        }
    }

    for (int ch = 0; ch < NC; ch++) {
        __syncthreads();
        #pragma unroll
        for (int i = 0; i < 4; i++) {
            int idx = t + i*256;
            int r = idx >> 3;
            int c4 = (idx & 7) * 4;
            uint4 ua = make_uint4(f2tf(aReg[i].x), f2tf(aReg[i].y), f2tf(aReg[i].z), f2tf(aReg[i].w));
            uint4 ub = make_uint4(f2tf(bReg[i].x), f2tf(bReg[i].y), f2tf(bReg[i].z), f2tf(bReg[i].w));
            *(uint4*)&As[r*SA + c4] = ua;
            *(uint4*)&Bs[r*SA + c4] = ub;
        }
        __syncthreads();

        if (ch + 1 < NC) {
            const int k0 = (ch + 1) * 32;
            #pragma unroll
            for (int i = 0; i < 4; i++) {
                int idx = t + i*256;
                int r = idx >> 3;
                int c4 = (idx & 7) * 4;
                aReg[i] = (k0 + c4 < K) ? *(const float4*)&A[(size_t)(bm + r)*lda + k0 + c4] : z4;
                int j = bn + r;
                bReg[i] = (j < Nc && k0 + c4 < K) ? *(const float4*)&W[(size_t)j*K + k0 + c4] : z4;
            }
        }

        #pragma unroll
        for (int ks = 0; ks < 4; ks++) {
            const int k0 = ks * 8;
            uint32_t afr[2][4];
            #pragma unroll
            for (int mt = 0; mt < 2; mt++) {
                int r0 = warp_m*32 + mt*16 + qr;
                afr[mt][0] = As[r0*SA + k0 + qc];
                afr[mt][1] = As[(r0+8)*SA + k0 + qc];
                afr[mt][2] = As[r0*SA + k0 + qc + 4];
                afr[mt][3] = As[(r0+8)*SA + k0 + qc + 4];
            }
            uint32_t bfr[8][2];
            #pragma unroll
            for (int nt = 0; nt < 8; nt++) {
                int n = warp_n*64 + nt*8 + qr;
                bfr[nt][0] = Bs[n*SA + k0 + qc];
                bfr[nt][1] = Bs[n*SA + k0 + qc + 4];
            }
            #pragma unroll
            for (int mt = 0; mt < 2; mt++)
                #pragma unroll
                for (int nt = 0; nt < 8; nt++)
                    mma_tf32(acc[mt][nt], afr[mt], bfr[nt]);
        }
    }

    // ---------------- epilogue (compile-time) ----------------
    if (MODE == 0) {
        #pragma unroll
        for (int mt = 0; mt < 2; mt++) {
            int r0 = bm + warp_m*32 + mt*16 + qr;
            #pragma unroll
            for (int nt = 0; nt < 8; nt++) {
                int c = bn + warp_n*64 + nt*8 + qc*2;
                if (c < Nc) {
                    *(float2*)&C[(size_t)r0*Nc + c]     = make_float2(acc[mt][nt][0], acc[mt][nt][1]);
                    *(float2*)&C[(size_t)(r0+8)*Nc + c] = make_float2(acc[mt][nt][2], acc[mt][nt][3]);
                }
            }
        }
    } else if (MODE == 1) {
        #pragma unroll
        for (int mt = 0; mt < 2; mt++) {
            int r0 = bm + warp_m*32 + mt*16 + qr;
            #pragma unroll
            for (int nt = 0; nt < 8; nt++) {
                int c = bn + warp_n*64 + nt*8 + qc*2;
                if (c < Nc) {
                    float b0 = p0[c], b1 = p0[c+1];
                    float v;
                    v = acc[mt][nt][0] + b0; v = (v > 20.f) ? v : log1pf(__expf(v));
                    C[(size_t)r0*Nc + c] = v;
                    v = acc[mt][nt][1] + b1; v = (v > 20.f) ? v : log1pf(__expf(v));
                    C[(size_t)r0*Nc + c + 1] = v;
                    v = acc[mt][nt][2] + b0; v = (v > 20.f) ? v : log1pf(__expf(v));
                    C[(size_t)(r0+8)*Nc + c] = v;
                    v = acc[mt][nt][3] + b1; v = (v > 20.f) ? v : log1pf(__expf(v));
                    C[(size_t)(r0+8)*Nc + c + 1] = v;
                }
            }
        }
    } else {
        #pragma unroll
        for (int mt = 0; mt < 2; mt++) {
            int rlo = bm + warp_m*32 + mt*16 + qr;
            int rhi = rlo + 8;
            float s0 = 0.f, ss0 = 0.f, s1 = 0.f, ss1 = 0.f;
            #pragma unroll
            for (int nt = 0; nt < 8; nt++) {
                int c = bn + warp_n*64 + nt*8 + qc*2;
                if (c < Nc) {
                    #pragma unroll
                    for (int h = 0; h < 2; h++) {
                        size_t i0 = (size_t)rlo*Nc + c + h;
                        float gate = 1.f / (1.f + __expf(-(p2[i0] + p3[c+h])));
                        float xfv = p1[i0] + acc[mt][nt][h]*gate + p0[i0];
                        C[i0] = xfv; s0 += xfv; ss0 += xfv*xfv;
                        size_t i1 = (size_t)rhi*Nc + c + h;
                        gate = 1.f / (1.f + __expf(-(p2[i1] + p3[c+h])));
                        xfv = p1[i1] + acc[mt][nt][h+2]*gate + p0[i1];
                        C[i1] = xfv; s1 += xfv; ss1 += xfv*xfv;
                    }
                }
            }
            atomicAdd(&paux0[rlo], s0); atomicAdd(&paux1[rlo], ss0);
            atomicAdd(&paux0[rhi], s1); atomicAdd(&paux1[rhi], ss1);
        }
    }
}

// ---------------- BatchNorm stats over all rows, per channel ----------------
// grid.x row-slices; each block handles all C channels for its rows.
__global__ void bn_stats(const float* __restrict__ X, int M, int C,
                         float* __restrict__ sum, float* __restrict__ sq)
{
    int c = blockIdx.y * blockDim.x + threadIdx.x;
    if (c >= C) return;
    int rows = M / gridDim.x;
    int r0 = blockIdx.x * rows;
    float s = 0.f, ss = 0.f;
    for (int r = r0; r < r0 + rows; r++) {
        float v = X[(size_t)r*C + c];
        s += v; ss += v*v;
    }
    atomicAdd(&sum[c], s);
    atomicAdd(&sq[c],  ss);
}

__global__ void bn_silu(const float* __restrict__ X, float* __restrict__ Y,
                        const float* __restrict__ sum, const float* __restrict__ sq,
                        const float* __restrict__ g, const float* __restrict__ b,
                        int M, int C)
{
    int idx = blockIdx.x * blockDim.x + threadIdx.x;
    if (idx >= M*C) return;
    int c = idx % C;
    float mean = sum[c] / (float)M;
    float var  = sq[c] / (float)M - mean*mean;
    float v = (X[idx] - mean) * rsqrtf(var + EPSq) * g[c] + b[c];
    Y[idx] = v / (1.f + __expf(-v));
}

// ---------------- dwconv5 fused with input-side bn+silu ----------------
__global__ void dwconv_fused(const float* __restrict__ X, const float* __restrict__ w,
                             const float* __restrict__ sum, const float* __restrict__ sq,
                             const float* __restrict__ g, const float* __restrict__ b,
                             float* __restrict__ Y)
{
    int idx = blockIdx.x * blockDim.x + threadIdx.x;
    if (idx >= Nq*HIDq) return;
    int c  = idx % HIDq;
    int l  = (idx / HIDq) % Lq;
    int bb = idx / (HIDq*Lq);
    float mean = sum[c] / (float)Nq;
    float var  = sq[c] / (float)Nq - mean*mean;
    float ga = rsqrtf(var + EPSq) * g[c];
    float be = b[c] - mean * ga;
    const float* xb = X + (size_t)bb*Lq*HIDq;
    float acc = 0.f;
    #pragma unroll
    for (int k = 0; k < 5; k++) {
        int ls = l - 2 + k;
        if (ls >= 0 && ls < Lq) {
            float v = xb[(size_t)ls*HIDq + c] * ga + be;
            acc += (v / (1.f + __expf(-v))) * w[c*5 + k];
        }
    }
    Y[idx] = acc;
}

// ---------------- bn_add + LN stats + LN apply, fused (block per row) ----------------
__global__ void __launch_bounds__(256) bn_add_ln(
    const float* __restrict__ E, const float* __restrict__ X,
    const float* __restrict__ sum3, const float* __restrict__ sq3,
    const float* __restrict__ exg, const float* __restrict__ exb,
    const float* __restrict__ lng, const float* __restrict__ lnb,
    float* __restrict__ X1, float* __restrict__ XN,
    float* __restrict__ rm, float* __restrict__ rs)
{
    const int row = blockIdx.x;
    const int tid = threadIdx.x;
    float vloc[3];
    float s = 0.f, ss = 0.f;
    #pragma unroll
    for (int j = 0; j < 3; j++) {
        int c = tid + j*256;
        float mean = sum3[c] / (float)Nq;
        float var  = sq3[c] / (float)Nq - mean*mean;
        float ga = rsqrtf(var + EPSq) * exg[c];
        float be = exb[c] - mean*ga;
        float v = X[(size_t)row*Dq + c] + E[(size_t)row*Dq + c]*ga + be;
        vloc[j] = v;
        s += v; ss += v*v;
    }
    __shared__ float sh1[8], sh2[8], bcast[2];
    for (int o = 16; o; o >>= 1) {
        s  += __shfl_down_sync(0xffffffffu, s, o);
        ss += __shfl_down_sync(0xffffffffu, ss, o);
    }
    int lane = tid & 31, warp = tid >> 5;
    if (lane == 0) { sh1[warp] = s; sh2[warp] = ss; }
    __syncthreads();
    if (tid == 0) {
        s = 0.f; ss = 0.f;
        #pragma unroll
        for (int wv = 0; wv < 8; wv++) { s += sh1[wv]; ss += sh2[wv]; }
        float m = s / (float)Dq;
        float v = ss / (float)Dq - m*m;
        float r = rsqrtf(v + EPSq);
        bcast[0] = m; bcast[1] = r;
        rm[row] = m; rs[row] = r;
    }
    __syncthreads();
    float m = bcast[0], r = bcast[1];
    #pragma unroll
    for (int j = 0; j < 3; j++) {
        int c = tid + j*256;
        X1[(size_t)row*Dq + c] = vloc[j];
        XN[(size_t)row*Dq + c] = (vloc[j] - m) * r * lng[c] + lnb[c];
    }
}

// ---------------- causal depthwise conv K=4 + bias + silu ----------------
__global__ void conv_causal_silu(const float* __restrict__ XZ, const float* __restrict__ w,
                                 const float* __restrict__ bias, float* __restrict__ Y)
{
    int idx = blockIdx.x * blockDim.x + threadIdx.x;
    if (idx >= Nq*DIq) return;
    int c  = idx % DIq;
    int l  = (idx / DIq) % Lq;
    int bb = idx / (DIq*Lq);
    float acc = bias[c];
    #pragma unroll
    for (int k = 0; k < 4; k++) {
        int ls = l - 3 + k;
        if (ls >= 0) acc += XZ[(size_t)(bb*Lq + ls)*(2*DIq) + c] * w[c*4 + k];
    }
    Y[idx] = acc / (1.f + __expf(-acc));
}

// feat_attr[b,c] = max_l LN(x1)[b,l,c]
__global__ void attr_max(const float* __restrict__ X, const float* __restrict__ mean,
                         const float* __restrict__ rstd, const float* __restrict__ g,
                         const float* __restrict__ b, float* __restrict__ out)
{
    int c  = blockIdx.y * blockDim.x + threadIdx.x;
    int bb = blockIdx.x;
    float gm = g[c], gb = b[c];
    float mx = -3.4e38f;
    for (int l = 0; l < Lq; l++) {
        int row = bb*Lq + l;
        float v = (X[(size_t)row*Dq + c] - mean[row]) * rstd[row] * gm + gb;
        mx = fmaxf(mx, v);
    }
    out[bb*Dq + c] = mx;
}

// ---------------- selective scan (prefetched) ----------------
__global__ void __launch_bounds__(256) scan_k(
    const float* __restrict__ delta, const float* __restrict__ u,
    const float* __restrict__ dbc,   const float* __restrict__ xz,
    const float* __restrict__ A_log, const float* __restrict__ Dp,
    float* __restrict__ y)
{
    __shared__ float Bs[128][DSq];
    __shared__ float Cs[128][DSq];
    const int bb = blockIdx.y;
    const int d  = blockIdx.x * 256 + threadIdx.x;

    float A[DSq], h[DSq];
    #pragma unroll
    for (int s = 0; s < DSq; s++) { A[s] = -expf(A_log[d*DSq + s]); h[s] = 0.f; }
    const float dp = Dp[d];

    for (int c0 = 0; c0 < Lq; c0 += 128) {
        for (int i = threadIdx.x; i < 128*DSq; i += 256) {
            int l = i >> 4, s = i & 15;
            size_t row = (size_t)(bb*Lq + c0 + l);
            Bs[l][s] = dbc[row*80 + DTRq + s];
            Cs[l][s] = dbc[row*80 + DTRq + DSq + s];
        }
        __syncthreads();
        size_t row0 = (size_t)(bb*Lq + c0);
        float dv = delta[row0*DIq + d];
        float uv = u[row0*DIq + d];
        float zv = xz[row0*(2*DIq) + DIq + d];
        for (int l = 0; l < 128; l++) {
            float nd = 0.f, nu = 0.f, nz = 0.f;
            if (l < 127) {
                size_t rn = row0 + l + 1;
                nd = delta[rn*DIq + d];
                nu = u[rn*DIq + d];
                nz = xz[rn*(2*DIq) + DIq + d];
            }
            float du = dv * uv;
            float acc = 0.f;
            #pragma unroll
            for (int s = 0; s < DSq; s++) {
                h[s] = h[s] * __expf(dv * A[s]) + du * Bs[l][s];
                acc  = fmaf(h[s], Cs[l][s], acc);
            }
            float sz = zv / (1.f + __expf(-zv));
            y[(row0 + l)*DIq + d] = (acc + uv*dp) * sz;
            dv = nd; uv = nu; zv = nz;
        }
        __syncthreads();
    }
}

// feat_id[b,c] = mean_l LN(xf)[b,l,c]
__global__ void feat_id_k(const float* __restrict__ X, const float* __restrict__ rowsum,
                          const float* __restrict__ rowsq, const float* __restrict__ g,
                          const float* __restrict__ b, float* __restrict__ fid,
                          float* __restrict__ out)
{
    int c  = blockIdx.y * blockDim.x + threadIdx.x;
    int bb = blockIdx.x;
    float gm = g[c], gb = b[c];
    float s = 0.f;
    for (int l = 0; l < Lq; l++) {
        int row = bb*Lq + l;
        float m = rowsum[row] / (float)Dq;
        float var = rowsq[row] / (float)Dq - m*m;
        float r = rsqrtf(var + EPSq);
        s += (X[(size_t)row*Dq + c] - m) * r * gm + gb;
    }
    float v = s / (float)Lq;
    fid[bb*Dq + c] = v;
    out[bb*Dq + c] = v;
}

__global__ void feat_bn(const float* __restrict__ fid, const float* __restrict__ g,
                        const float* __restrict__ b, float* __restrict__ out)
{
    int c = blockIdx.x * blockDim.x + threadIdx.x;
    if (c >= Dq) return;
    float s = 0.f, ss = 0.f;
    for (int bb = 0; bb < Bq; bb++) {
        float v = fid[bb*Dq + c]; s += v; ss += v*v;
    }
    float m = s / (float)Bq;
    float var = ss / (float)Bq - m*m;
    float rs = rsqrtf(var + EPSq);
    for (int bb = 0; bb < Bq; bb++)
        out[bb*Dq + c] = (fid[bb*Dq + c] - m) * rs * g[c] + b[c];
}

// ---------------- host ----------------
#define GETSYM(p, s) { void* _t; cudaGetSymbolAddress(&_t, s); p = (float*)_t; }

extern "C" void kernel_launch(void* const* d_in, const int* in_sizes, int n_in,
                              void* d_out, int out_size)
{
    const float* x        = (const float*)d_in[0];
    const float* sq_w     = (const float*)d_in[1];
    const float* sq_bn_g  = (const float*)d_in[2];
    const float* sq_bn_b  = (const float*)d_in[3];
    const float* dw_w     = (const float*)d_in[4];
    const float* dw_bn_g  = (const float*)d_in[5];
    const float* dw_bn_b  = (const float*)d_in[6];
    const float* ex_w     = (const float*)d_in[7];
    const float* ex_bn_g  = (const float*)d_in[8];
    const float* ex_bn_b  = (const float*)d_in[9];
    const float* attr_g   = (const float*)d_in[10];
    const float* attr_b   = (const float*)d_in[11];
    const float* mnorm_g  = (const float*)d_in[12];
    const float* mnorm_b  = (const float*)d_in[13];
    const float* in_proj_w= (const float*)d_in[14];
    const float* conv_w   = (const float*)d_in[15];
    const float* conv_b   = (const float*)d_in[16];
    const float* xproj_w  = (const float*)d_in[17];
    const float* dtproj_w = (const float*)d_in[18];
    const float* dtproj_b = (const float*)d_in[19];
    const float* A_log    = (const float*)d_in[20];
    const float* D_param  = (const float*)d_in[21];
    const float* out_proj_w = (const float*)d_in[22];
    const float* gate_w   = (const float*)d_in[23];
    const float* gate_b   = (const float*)d_in[24];
    const float* idn_g    = (const float*)d_in[25];
    const float* idn_b    = (const float*)d_in[26];
    const float* idbn_g   = (const float*)d_in[27];
    const float* idbn_b   = (const float*)d_in[28];
    float* out = (float*)d_out;

    float *h0,*tmpH,*h2,*e,*x1,*xn,*xz,*xm2,*dbc,*del,*y,*gl,*xf;
    float *rm,*rs,*fid,*stats;
    GETSYM(h0, g_h0);   GETSYM(tmpH, g_tmpH); GETSYM(h2, g_h2);
    GETSYM(e, g_e);     GETSYM(x1, g_x1);     GETSYM(xn, g_xn);
    GETSYM(xz, g_xz);   GETSYM(xm2, g_xm2);   GETSYM(dbc, g_dbc);
    GETSYM(del, g_del); GETSYM(y, g_y);       GETSYM(gl, g_gl);
    GETSYM(xf, g_xf);   GETSYM(rm, g_rm);     GETSYM(rs, g_rs);
    GETSYM(fid, g_fid); GETSYM(stats, g_stats);

    float* rowsum = stats + ST_ROWSUM;
    float* rowsq  = stats + ST_ROWSQ;
    float* sum1   = stats + ST_SUM1;
    float* sq1    = stats + ST_SQ1;
    float* sum2   = stats + ST_SUM2;
    float* sq2    = stats + ST_SQ2;
    float* sum3   = stats + ST_SUM3;
    float* sq3    = stats + ST_SQ3;

    const int T = 256;
    dim3 gHID((Nq*HIDq + T-1)/T), gDI((Nq*DIq + T-1)/T);

    // 0) zero stats
    cudaMemsetAsync(stats, 0, ST_TOTAL*sizeof(float));

    // 1) squeeze GEMM + bn stats
    gemm_tc<0><<<dim3(2, Nq/128), 256>>>(x, Dq, sq_w, h0, HIDq, Dq, 0,0,0,0,0,0);
    bn_stats<<<dim3(256,1), T>>>(h0, Nq, HIDq, sum1, sq1);

    // 2) dwconv(silu(bn1(.))) + bn stats + bn_silu -> h2
    dwconv_fused<<<gHID, T>>>(h0, dw_w, sum1, sq1, sq_bn_g, sq_bn_b, tmpH);
    bn_stats<<<dim3(256,1), T>>>(tmpH, Nq, HIDq, sum2, sq2);
    bn_silu<<<gHID, T>>>(tmpH, h2, sum2, sq2, dw_bn_g, dw_bn_b, Nq, HIDq);

    // 3) excite GEMM + bn stats; fused bn_add + LN
    gemm_tc<0><<<dim3(6, Nq/128), 256>>>(h2, HIDq, ex_w, e, Dq, HIDq, 0,0,0,0,0,0);
    bn_stats<<<dim3(256,3), T>>>(e, Nq, Dq, sum3, sq3);
    bn_add_ln<<<Nq, T>>>(e, x, sum3, sq3, ex_bn_g, ex_bn_b, mnorm_g, mnorm_b,
                         x1, xn, rm, rs);

    // 4) feat_attr
    attr_max<<<dim3(Bq,3), T>>>(x1, rm, rs, attr_g, attr_b, out);

    // 5) Mamba in_proj
    gemm_tc<0><<<dim3(24, Nq/128), 256>>>(xn, Dq, in_proj_w, xz, 2*DIq, Dq, 0,0,0,0,0,0);

    // 6) causal conv + silu -> xm2
    conv_causal_silu<<<gDI, T>>>(xz, conv_w, conv_b, xm2);

    // 7) x_proj -> dbc ; dt_proj (+softplus epilogue) -> del
    gemm_tc<0><<<dim3(1, Nq/128), 256>>>(xm2, DIq, xproj_w, dbc, 80, DIq, 0,0,0,0,0,0);
    gemm_tc<1><<<dim3(12, Nq/128), 256>>>(dbc, 80, dtproj_w, del, DIq, DTRq,
                                          dtproj_b, 0,0,0,0,0);

    // 8) selective scan
    scan_k<<<dim3(DIq/256, Bq), 256>>>(del, xm2, dbc, xz, A_log, D_param, y);

    // 9) gate GEMM; out_proj GEMM with fused combine + row stats
    gemm_tc<0><<<dim3(6, Nq/128), 256>>>(xn, Dq, gate_w, gl, Dq, Dq, 0,0,0,0,0,0);
    gemm_tc<2><<<dim3(6, Nq/128), 256>>>(y, DIq, out_proj_w, xf, Dq, DIq,
                                         x, x1, gl, gate_b, rowsum, rowsq);

    // 10) feat_id + feat_id_bn
    feat_id_k<<<dim3(Bq,3), T>>>(xf, rowsum, rowsq, idn_g, idn_b, fid, out + Bq*Dq);
    feat_bn<<<3, T>>>(fid, idbn_g, idbn_b, out + 2*Bq*Dq);
}

// round 7
// speedup vs baseline: 1.6866x; 1.1351x over previous
#include <cuda_runtime.h>
#include <math.h>
#include <stdint.h>

#define Bq    32
#define Lq    512
#define Dq    768
#define HIDq  192
#define DIq   1536
#define DSq   16
#define DTRq  48
#define Nq    (Bq*Lq)        // 16384
#define EPSq  1e-5f

// ---------------- scratch ----------------
__device__ __align__(256) float g_h0  [Nq*HIDq];
__device__ __align__(256) float g_tmpH[Nq*HIDq];
__device__ __align__(256) float g_h2  [Nq*HIDq];
__device__ __align__(256) float g_e   [Nq*Dq];
__device__ __align__(256) float g_x1  [Nq*Dq];
__device__ __align__(256) float g_xn  [Nq*Dq];
__device__ __align__(256) float g_xz  [Nq*2*DIq];
__device__ __align__(256) float g_xm2 [Nq*DIq];
__device__ __align__(256) float g_dbc [Nq*80];
__device__ __align__(256) float g_del [Nq*DIq];
__device__ __align__(256) float g_y   [Nq*DIq];
__device__ __align__(256) float g_mo  [Nq*Dq];
__device__ __align__(256) float g_gl  [Nq*Dq];
__device__ __align__(256) float g_xf  [Nq*Dq];
__device__ __align__(256) float g_rm  [Nq];
__device__ __align__(256) float g_rs  [Nq];
__device__ __align__(256) float g_rm2 [Nq];
__device__ __align__(256) float g_rs2 [Nq];
__device__ __align__(256) float g_fid [Bq*Dq];
#define ST_SUM1   0
#define ST_SQ1    (ST_SUM1+192)
#define ST_SUM2   (ST_SQ1+192)
#define ST_SQ2    (ST_SUM2+192)
#define ST_SUM3   (ST_SQ2+192)
#define ST_SQ3    (ST_SUM3+768)
#define ST_TOTAL  (ST_SQ3+768)
__device__ __align__(256) float g_stats[ST_TOTAL];

// ================= TF32 mma.sync GEMM (templated epilogue) =================
// C[M,Nc] = A[M,K](lda) @ W[Nc,K]^T.  BM=128, BN=128, BK=32.
// MODE 0: plain store. MODE 1: softplus(v + p0[c]).
#define SA 36

__device__ __forceinline__ uint32_t f2tf(float f) {
    uint32_t u;
    asm("cvt.rna.tf32.f32 %0, %1;" : "=r"(u) : "f"(f));
    return u;
}

__device__ __forceinline__ void mma_tf32(float* d, const uint32_t* a, const uint32_t* b) {
    asm volatile(
        "mma.sync.aligned.m16n8k8.row.col.f32.tf32.tf32.f32 "
        "{%0,%1,%2,%3}, {%4,%5,%6,%7}, {%8,%9}, {%0,%1,%2,%3};"
        : "+f"(d[0]), "+f"(d[1]), "+f"(d[2]), "+f"(d[3])
        : "r"(a[0]), "r"(a[1]), "r"(a[2]), "r"(a[3]), "r"(b[0]), "r"(b[1]));
}

template<int MODE>
__global__ void __launch_bounds__(256) gemm_tc(
    const float* __restrict__ A, int lda,
    const float* __restrict__ W,
    float* __restrict__ C, int Nc, int K,
    const float* __restrict__ p0)
{
    __shared__ uint32_t As[128*SA];
    __shared__ uint32_t Bs[128*SA];

    const int bm = blockIdx.y * 128;
    const int bn = blockIdx.x * 128;
    const int t  = threadIdx.x;
    const int wid  = t >> 5;
    const int lane = t & 31;
    const int qr = lane >> 2;
    const int qc = lane & 3;
    const int warp_m = wid & 3;
    const int warp_n = wid >> 2;

    float acc[2][8][4];
    #pragma unroll
    for (int mt = 0; mt < 2; mt++)
        #pragma unroll
        for (int nt = 0; nt < 8; nt++)
            #pragma unroll
            for (int q = 0; q < 4; q++) acc[mt][nt][q] = 0.f;

    const int NC = (K + 31) / 32;

    float4 aReg[4], bReg[4];
    const float4 z4 = make_float4(0.f, 0.f, 0.f, 0.f);

    {
        #pragma unroll
        for (int i = 0; i < 4; i++) {
            int idx = t + i*256;
            int r = idx >> 3;
            int c4 = (idx & 7) * 4;
            aReg[i] = (c4 < K) ? *(const float4*)&A[(size_t)(bm + r)*lda + c4] : z4;
            int j = bn + r;
            bReg[i] = (j < Nc && c4 < K) ? *(const float4*)&W[(size_t)j*K + c4] : z4;
        }
    }

    for (int ch = 0; ch < NC; ch++) {
        __syncthreads();
        #pragma unroll
        for (int i = 0; i < 4; i++) {
            int idx = t + i*256;
            int r = idx >> 3;
            int c4 = (idx & 7) * 4;
            uint4 ua = make_uint4(f2tf(aReg[i].x), f2tf(aReg[i].y), f2tf(aReg[i].z), f2tf(aReg[i].w));
            uint4 ub = make_uint4(f2tf(bReg[i].x), f2tf(bReg[i].y), f2tf(bReg[i].z), f2tf(bReg[i].w));
            *(uint4*)&As[r*SA + c4] = ua;
            *(uint4*)&Bs[r*SA + c4] = ub;
        }
        __syncthreads();

        if (ch + 1 < NC) {
            const int k0 = (ch + 1) * 32;
            #pragma unroll
            for (int i = 0; i < 4; i++) {
                int idx = t + i*256;
                int r = idx >> 3;
                int c4 = (idx & 7) * 4;
                aReg[i] = (k0 + c4 < K) ? *(const float4*)&A[(size_t)(bm + r)*lda + k0 + c4] : z4;
                int j = bn + r;
                bReg[i] = (j < Nc && k0 + c4 < K) ? *(const float4*)&W[(size_t)j*K + k0 + c4] : z4;
            }
        }

        #pragma unroll
        for (int ks = 0; ks < 4; ks++) {
            const int k0 = ks * 8;
            uint32_t afr[2][4];
            #pragma unroll
            for (int mt = 0; mt < 2; mt++) {
                int r0 = warp_m*32 + mt*16 + qr;
                afr[mt][0] = As[r0*SA + k0 + qc];
                afr[mt][1] = As[(r0+8)*SA + k0 + qc];
                afr[mt][2] = As[r0*SA + k0 + qc + 4];
                afr[mt][3] = As[(r0+8)*SA + k0 + qc + 4];
            }
            uint32_t bfr[8][2];
            #pragma unroll
            for (int nt = 0; nt < 8; nt++) {
                int n = warp_n*64 + nt*8 + qr;
                bfr[nt][0] = Bs[n*SA + k0 + qc];
                bfr[nt][1] = Bs[n*SA + k0 + qc + 4];
            }
            #pragma unroll
            for (int mt = 0; mt < 2; mt++)
                #pragma unroll
                for (int nt = 0; nt < 8; nt++)
                    mma_tf32(acc[mt][nt], afr[mt], bfr[nt]);
        }
    }

    if (MODE == 0) {
        #pragma unroll
        for (int mt = 0; mt < 2; mt++) {
            int r0 = bm + warp_m*32 + mt*16 + qr;
            #pragma unroll
            for (int nt = 0; nt < 8; nt++) {
                int c = bn + warp_n*64 + nt*8 + qc*2;
                if (c < Nc) {
                    *(float2*)&C[(size_t)r0*Nc + c]     = make_float2(acc[mt][nt][0], acc[mt][nt][1]);
                    *(float2*)&C[(size_t)(r0+8)*Nc + c] = make_float2(acc[mt][nt][2], acc[mt][nt][3]);
                }
            }
        }
    } else {
        #pragma unroll
        for (int mt = 0; mt < 2; mt++) {
            int r0 = bm + warp_m*32 + mt*16 + qr;
            #pragma unroll
            for (int nt = 0; nt < 8; nt++) {
                int c = bn + warp_n*64 + nt*8 + qc*2;
                if (c < Nc) {
                    float b0 = p0[c], b1 = p0[c+1];
                    float v;
                    v = acc[mt][nt][0] + b0; v = (v > 20.f) ? v : log1pf(__expf(v));
                    C[(size_t)r0*Nc + c] = v;
                    v = acc[mt][nt][1] + b1; v = (v > 20.f) ? v : log1pf(__expf(v));
                    C[(size_t)r0*Nc + c + 1] = v;
                    v = acc[mt][nt][2] + b0; v = (v > 20.f) ? v : log1pf(__expf(v));
                    C[(size_t)(r0+8)*Nc + c] = v;
                    v = acc[mt][nt][3] + b1; v = (v > 20.f) ? v : log1pf(__expf(v));
                    C[(size_t)(r0+8)*Nc + c + 1] = v;
                }
            }
        }
    }
}

// ---------------- BatchNorm stats (grid.x = 256 row slices) ----------------
__global__ void bn_stats(const float* __restrict__ X, int M, int C,
                         float* __restrict__ sum, float* __restrict__ sq)
{
    int c = blockIdx.y * blockDim.x + threadIdx.x;
    if (c >= C) return;
    int rows = M / gridDim.x;
    int r0 = blockIdx.x * rows;
    float s = 0.f, ss = 0.f;
    for (int r = r0; r < r0 + rows; r++) {
        float v = X[(size_t)r*C + c];
        s += v; ss += v*v;
    }
    atomicAdd(&sum[c], s);
    atomicAdd(&sq[c],  ss);
}

__global__ void bn_silu(const float* __restrict__ X, float* __restrict__ Y,
                        const float* __restrict__ sum, const float* __restrict__ sq,
                        const float* __restrict__ g, const float* __restrict__ b,
                        int M, int C)
{
    int idx = blockIdx.x * blockDim.x + threadIdx.x;
    if (idx >= M*C) return;
    int c = idx % C;
    float mean = sum[c] / (float)M;
    float var  = sq[c] / (float)M - mean*mean;
    float v = (X[idx] - mean) * rsqrtf(var + EPSq) * g[c] + b[c];
    Y[idx] = v / (1.f + __expf(-v));
}

// ---------------- depthwise conv K=5, same padding ----------------
__global__ void dwconv5(const float* __restrict__ X, const float* __restrict__ w,
                        float* __restrict__ Y)
{
    int idx = blockIdx.x * blockDim.x + threadIdx.x;
    if (idx >= Nq*HIDq) return;
    int c  = idx % HIDq;
    int l  = (idx / HIDq) % Lq;
    int bb = idx / (HIDq*Lq);
    const float* xb = X + (size_t)bb*Lq*HIDq;
    float acc = 0.f;
    #pragma unroll
    for (int k = 0; k < 5; k++) {
        int ls = l - 2 + k;
        if (ls >= 0 && ls < Lq) acc += xb[(size_t)ls*HIDq + c] * w[c*5 + k];
    }
    Y[idx] = acc;
}

// ---------------- bn_add + LN stats + LN apply, fused (block per row) ----------------
__global__ void __launch_bounds__(256) bn_add_ln(
    const float* __restrict__ E, const float* __restrict__ X,
    const float* __restrict__ sum3, const float* __restrict__ sq3,
    const float* __restrict__ exg, const float* __restrict__ exb,
    const float* __restrict__ lng, const float* __restrict__ lnb,
    float* __restrict__ X1, float* __restrict__ XN,
    float* __restrict__ rm, float* __restrict__ rs)
{
    const int row = blockIdx.x;
    const int tid = threadIdx.x;
    float vloc[3];
    float s = 0.f, ss = 0.f;
    #pragma unroll
    for (int j = 0; j < 3; j++) {
        int c = tid + j*256;
        float mean = sum3[c] / (float)Nq;
        float var  = sq3[c] / (float)Nq - mean*mean;
        float ga = rsqrtf(var + EPSq) * exg[c];
        float be = exb[c] - mean*ga;
        float v = X[(size_t)row*Dq + c] + E[(size_t)row*Dq + c]*ga + be;
        vloc[j] = v;
        s += v; ss += v*v;
    }
    __shared__ float sh1[8], sh2[8], bcast[2];
    for (int o = 16; o; o >>= 1) {
        s  += __shfl_down_sync(0xffffffffu, s, o);
        ss += __shfl_down_sync(0xffffffffu, ss, o);
    }
    int lane = tid & 31, warp = tid >> 5;
    if (lane == 0) { sh1[warp] = s; sh2[warp] = ss; }
    __syncthreads();
    if (tid == 0) {
        s = 0.f; ss = 0.f;
        #pragma unroll
        for (int wv = 0; wv < 8; wv++) { s += sh1[wv]; ss += sh2[wv]; }
        float m = s / (float)Dq;
        float v = ss / (float)Dq - m*m;
        float r = rsqrtf(v + EPSq);
        bcast[0] = m; bcast[1] = r;
        rm[row] = m; rs[row] = r;
    }
    __syncthreads();
    float m = bcast[0], r = bcast[1];
    #pragma unroll
    for (int j = 0; j < 3; j++) {
        int c = tid + j*256;
        X1[(size_t)row*Dq + c] = vloc[j];
        XN[(size_t)row*Dq + c] = (vloc[j] - m) * r * lng[c] + lnb[c];
    }
}

// ---------------- combine + LN stats, fused (block per row) ----------------
// xf = x1 + mo*sigmoid(gl + gb) + x ; rm2/rs2 = LN stats of xf
__global__ void __launch_bounds__(256) combine_ln(
    const float* __restrict__ X, const float* __restrict__ X1,
    const float* __restrict__ MO, const float* __restrict__ GL,
    const float* __restrict__ gb,
    float* __restrict__ XF, float* __restrict__ rm2, float* __restrict__ rs2)
{
    const int row = blockIdx.x;
    const int tid = threadIdx.x;
    float vloc[3];
    float s = 0.f, ss = 0.f;
    #pragma unroll
    for (int j = 0; j < 3; j++) {
        int c = tid + j*256;
        size_t i = (size_t)row*Dq + c;
        float gate = 1.f / (1.f + __expf(-(GL[i] + gb[c])));
        float v = X1[i] + MO[i]*gate + X[i];
        vloc[j] = v;
        s += v; ss += v*v;
    }
    __shared__ float sh1[8], sh2[8];
    for (int o = 16; o; o >>= 1) {
        s  += __shfl_down_sync(0xffffffffu, s, o);
        ss += __shfl_down_sync(0xffffffffu, ss, o);
    }
    int lane = tid & 31, warp = tid >> 5;
    if (lane == 0) { sh1[warp] = s; sh2[warp] = ss; }
    __syncthreads();
    if (tid == 0) {
        s = 0.f; ss = 0.f;
        #pragma unroll
        for (int wv = 0; wv < 8; wv++) { s += sh1[wv]; ss += sh2[wv]; }
        float m = s / (float)Dq;
        float v = ss / (float)Dq - m*m;
        rm2[row] = m;
        rs2[row] = rsqrtf(v + EPSq);
    }
    #pragma unroll
    for (int j = 0; j < 3; j++) {
        int c = tid + j*256;
        XF[(size_t)row*Dq + c] = vloc[j];
    }
}

// ---------------- causal depthwise conv K=4 + bias + silu ----------------
__global__ void conv_causal_silu(const float* __restrict__ XZ, const float* __restrict__ w,
                                 const float* __restrict__ bias, float* __restrict__ Y)
{
    int idx = blockIdx.x * blockDim.x + threadIdx.x;
    if (idx >= Nq*DIq) return;
    int c  = idx % DIq;
    int l  = (idx / DIq) % Lq;
    int bb = idx / (DIq*Lq);
    float acc = bias[c];
    #pragma unroll
    for (int k = 0; k < 4; k++) {
        int ls = l - 3 + k;
        if (ls >= 0) acc += XZ[(size_t)(bb*Lq + ls)*(2*DIq) + c] * w[c*4 + k];
    }
    Y[idx] = acc / (1.f + __expf(-acc));
}

// feat_attr[b,c] = max_l LN(x1)[b,l,c]
__global__ void attr_max(const float* __restrict__ X, const float* __restrict__ mean,
                         const float* __restrict__ rstd, const float* __restrict__ g,
                         const float* __restrict__ b, float* __restrict__ out)
{
    int c  = blockIdx.y * blockDim.x + threadIdx.x;
    int bb = blockIdx.x;
    float gm = g[c], gb = b[c];
    float mx = -3.4e38f;
    for (int l = 0; l < Lq; l++) {
        int row = bb*Lq + l;
        float v = (X[(size_t)row*Dq + c] - mean[row]) * rstd[row] * gm + gb;
        mx = fmaxf(mx, v);
    }
    out[bb*Dq + c] = mx;
}

// ---------------- selective scan (prefetched) ----------------
__global__ void __launch_bounds__(256) scan_k(
    const float* __restrict__ delta, const float* __restrict__ u,
    const float* __restrict__ dbc,   const float* __restrict__ xz,
    const float* __restrict__ A_log, const float* __restrict__ Dp,
    float* __restrict__ y)
{
    __shared__ float Bs[128][DSq];
    __shared__ float Cs[128][DSq];
    const int bb = blockIdx.y;
    const int d  = blockIdx.x * 256 + threadIdx.x;

    float A[DSq], h[DSq];
    #pragma unroll
    for (int s = 0; s < DSq; s++) { A[s] = -expf(A_log[d*DSq + s]); h[s] = 0.f; }
    const float dp = Dp[d];

    for (int c0 = 0; c0 < Lq; c0 += 128) {
        for (int i = threadIdx.x; i < 128*DSq; i += 256) {
            int l = i >> 4, s = i & 15;
            size_t row = (size_t)(bb*Lq + c0 + l);
            Bs[l][s] = dbc[row*80 + DTRq + s];
            Cs[l][s] = dbc[row*80 + DTRq + DSq + s];
        }
        __syncthreads();
        size_t row0 = (size_t)(bb*Lq + c0);
        float dv = delta[row0*DIq + d];
        float uv = u[row0*DIq + d];
        float zv = xz[row0*(2*DIq) + DIq + d];
        for (int l = 0; l < 128; l++) {
            float nd = 0.f, nu = 0.f, nz = 0.f;
            if (l < 127) {
                size_t rn = row0 + l + 1;
                nd = delta[rn*DIq + d];
                nu = u[rn*DIq + d];
                nz = xz[rn*(2*DIq) + DIq + d];
            }
            float du = dv * uv;
            float acc = 0.f;
            #pragma unroll
            for (int s = 0; s < DSq; s++) {
                h[s] = h[s] * __expf(dv * A[s]) + du * Bs[l][s];
                acc  = fmaf(h[s], Cs[l][s], acc);
            }
            float sz = zv / (1.f + __expf(-zv));
            y[(row0 + l)*DIq + d] = (acc + uv*dp) * sz;
            dv = nd; uv = nu; zv = nz;
        }
        __syncthreads();
    }
}

// feat_id[b,c] = mean_l LN(xf)[b,l,c]
__global__ void feat_id_k(const float* __restrict__ X, const float* __restrict__ mean,
                          const float* __restrict__ rstd, const float* __restrict__ g,
                          const float* __restrict__ b, float* __restrict__ fid,
                          float* __restrict__ out)
{
    int c  = blockIdx.y * blockDim.x + threadIdx.x;
    int bb = blockIdx.x;
    float gm = g[c], gb = b[c];
    float s = 0.f;
    for (int l = 0; l < Lq; l++) {
        int row = bb*Lq + l;
        s += (X[(size_t)row*Dq + c] - mean[row]) * rstd[row] * gm + gb;
    }
    float v = s / (float)Lq;
    fid[bb*Dq + c] = v;
    out[bb*Dq + c] = v;
}

__global__ void feat_bn(const float* __restrict__ fid, const float* __restrict__ g,
                        const float* __restrict__ b, float* __restrict__ out)
{
    int c = blockIdx.x * blockDim.x + threadIdx.x;
    if (c >= Dq) return;
    float s = 0.f, ss = 0.f;
    for (int bb = 0; bb < Bq; bb++) {
        float v = fid[bb*Dq + c]; s += v; ss += v*v;
    }
    float m = s / (float)Bq;
    float var = ss / (float)Bq - m*m;
    float rs = rsqrtf(var + EPSq);
    for (int bb = 0; bb < Bq; bb++)
        out[bb*Dq + c] = (fid[bb*Dq + c] - m) * rs * g[c] + b[c];
}

// ---------------- host ----------------
#define GETSYM(p, s) { void* _t; cudaGetSymbolAddress(&_t, s); p = (float*)_t; }

extern "C" void kernel_launch(void* const* d_in, const int* in_sizes, int n_in,
                              void* d_out, int out_size)
{
    const float* x        = (const float*)d_in[0];
    const float* sq_w     = (const float*)d_in[1];
    const float* sq_bn_g  = (const float*)d_in[2];
    const float* sq_bn_b  = (const float*)d_in[3];
    const float* dw_w     = (const float*)d_in[4];
    const float* dw_bn_g  = (const float*)d_in[5];
    const float* dw_bn_b  = (const float*)d_in[6];
    const float* ex_w     = (const float*)d_in[7];
    const float* ex_bn_g  = (const float*)d_in[8];
    const float* ex_bn_b  = (const float*)d_in[9];
    const float* attr_g   = (const float*)d_in[10];
    const float* attr_b   = (const float*)d_in[11];
    const float* mnorm_g  = (const float*)d_in[12];
    const float* mnorm_b  = (const float*)d_in[13];
    const float* in_proj_w= (const float*)d_in[14];
    const float* conv_w   = (const float*)d_in[15];
    const float* conv_b   = (const float*)d_in[16];
    const float* xproj_w  = (const float*)d_in[17];
    const float* dtproj_w = (const float*)d_in[18];
    const float* dtproj_b = (const float*)d_in[19];
    const float* A_log    = (const float*)d_in[20];
    const float* D_param  = (const float*)d_in[21];
    const float* out_proj_w = (const float*)d_in[22];
    const float* gate_w   = (const float*)d_in[23];
    const float* gate_b   = (const float*)d_in[24];
    const float* idn_g    = (const float*)d_in[25];
    const float* idn_b    = (const float*)d_in[26];
    const float* idbn_g   = (const float*)d_in[27];
    const float* idbn_b   = (const float*)d_in[28];
    float* out = (float*)d_out;

    float *h0,*tmpH,*h2,*e,*x1,*xn,*xz,*xm2,*dbc,*del,*y,*mo,*gl,*xf;
    float *rm,*rs,*rm2,*rs2,*fid,*stats;
    GETSYM(h0, g_h0);   GETSYM(tmpH, g_tmpH); GETSYM(h2, g_h2);
    GETSYM(e, g_e);     GETSYM(x1, g_x1);     GETSYM(xn, g_xn);
    GETSYM(xz, g_xz);   GETSYM(xm2, g_xm2);   GETSYM(dbc, g_dbc);
    GETSYM(del, g_del); GETSYM(y, g_y);       GETSYM(mo, g_mo);
    GETSYM(gl, g_gl);   GETSYM(xf, g_xf);
    GETSYM(rm, g_rm);   GETSYM(rs, g_rs);     GETSYM(rm2, g_rm2); GETSYM(rs2, g_rs2);
    GETSYM(fid, g_fid); GETSYM(stats, g_stats);

    float* sum1 = stats + ST_SUM1;
    float* sq1  = stats + ST_SQ1;
    float* sum2 = stats + ST_SUM2;
    float* sq2  = stats + ST_SQ2;
    float* sum3 = stats + ST_SUM3;
    float* sq3  = stats + ST_SQ3;

    const int T = 256;
    dim3 gHID((Nq*HIDq + T-1)/T), gDI((Nq*DIq + T-1)/T);

    cudaMemsetAsync(stats, 0, ST_TOTAL*sizeof(float));

    // 1) squeeze GEMM + BN+SiLU
    gemm_tc<0><<<dim3(2, Nq/128), 256>>>(x, Dq, sq_w, h0, HIDq, Dq, 0);
    bn_stats<<<dim3(256,1), T>>>(h0, Nq, HIDq, sum1, sq1);
    bn_silu<<<gHID, T>>>(h0, h0, sum1, sq1, sq_bn_g, sq_bn_b, Nq, HIDq);

    // 2) dwconv K=5 + BN+SiLU
    dwconv5<<<gHID, T>>>(h0, dw_w, tmpH);
    bn_stats<<<dim3(256,1), T>>>(tmpH, Nq, HIDq, sum2, sq2);
    bn_silu<<<gHID, T>>>(tmpH, h2, sum2, sq2, dw_bn_g, dw_bn_b, Nq, HIDq);

    // 3) excite GEMM + fused bn_add + LN
    gemm_tc<0><<<dim3(6, Nq/128), 256>>>(h2, HIDq, ex_w, e, Dq, HIDq, 0);
    bn_stats<<<dim3(256,3), T>>>(e, Nq, Dq, sum3, sq3);
    bn_add_ln<<<Nq, T>>>(e, x, sum3, sq3, ex_bn_g, ex_bn_b, mnorm_g, mnorm_b,
                         x1, xn, rm, rs);

    // 4) feat_attr
    attr_max<<<dim3(Bq,3), T>>>(x1, rm, rs, attr_g, attr_b, out);

    // 5) Mamba in_proj
    gemm_tc<0><<<dim3(24, Nq/128), 256>>>(xn, Dq, in_proj_w, xz, 2*DIq, Dq, 0);

    // 6) causal conv + silu
    conv_causal_silu<<<gDI, T>>>(xz, conv_w, conv_b, xm2);

    // 7) x_proj; dt_proj (+softplus epilogue)
    gemm_tc<0><<<dim3(1, Nq/128), 256>>>(xm2, DIq, xproj_w, dbc, 80, DIq, 0);
    gemm_tc<1><<<dim3(12, Nq/128), 256>>>(dbc, 80, dtproj_w, del, DIq, DTRq, dtproj_b);

    // 8) selective scan
    scan_k<<<dim3(DIq/256, Bq), 256>>>(del, xm2, dbc, xz, A_log, D_param, y);

    // 9) out_proj, gate GEMMs; fused combine + LN stats
    gemm_tc<0><<<dim3(6, Nq/128), 256>>>(y, DIq, out_proj_w, mo, Dq, DIq, 0);
    gemm_tc<0><<<dim3(6, Nq/128), 256>>>(xn, Dq, gate_w, gl, Dq, Dq, 0);
    combine_ln<<<Nq, T>>>(x, x1, mo, gl, gate_b, xf, rm2, rs2);

    // 10) feat_id + feat_id_bn
    feat_id_k<<<dim3(Bq,3), T>>>(xf, rm2, rs2, idn_g, idn_b, fid, out + Bq*Dq);
    feat_bn<<<3, T>>>(fid, idbn_g, idbn_b, out + 2*Bq*Dq);
}

// round 8
// speedup vs baseline: 2.0207x; 1.1981x over previous
#include <cuda_runtime.h>
#include <math.h>
#include <stdint.h>

#define Bq    32
#define Lq    512
#define Dq    768
#define HIDq  192
#define DIq   1536
#define DSq   16
#define DTRq  48
#define Nq    (Bq*Lq)        // 16384
#define EPSq  1e-5f

// ---------------- scratch ----------------
__device__ __align__(256) float g_h0  [Nq*HIDq];
__device__ __align__(256) float g_tmpH[Nq*HIDq];
__device__ __align__(256) float g_h2  [Nq*HIDq];
__device__ __align__(256) float g_e   [Nq*Dq];
__device__ __align__(256) float g_x1  [Nq*Dq];
__device__ __align__(256) float g_xn  [Nq*Dq];
__device__ __align__(256) float g_xz  [Nq*2*DIq];
__device__ __align__(256) float g_xm2 [Nq*DIq];
__device__ __align__(256) float g_dbc [Nq*80];
__device__ __align__(256) float g_del [Nq*DIq];
__device__ __align__(256) float g_y   [Nq*DIq];
__device__ __align__(256) float g_mo  [Nq*Dq];
__device__ __align__(256) float g_gl  [Nq*Dq];
__device__ __align__(256) float g_xf  [Nq*Dq];
__device__ __align__(256) float g_rm  [Nq];
__device__ __align__(256) float g_rs  [Nq];
__device__ __align__(256) float g_rm2 [Nq];
__device__ __align__(256) float g_rs2 [Nq];
__device__ __align__(256) float g_fid [Bq*Dq];
#define ST_SUM1   0
#define ST_SQ1    (ST_SUM1+192)
#define ST_SUM2   (ST_SQ1+192)
#define ST_SQ2    (ST_SUM2+192)
#define ST_SUM3   (ST_SQ2+192)
#define ST_SQ3    (ST_SUM3+768)
#define ST_TOTAL  (ST_SQ3+768)
__device__ __align__(256) float g_stats[ST_TOTAL];

// ================= TF32 mma.sync GEMM (double-buffered smem, 1 sync/chunk) =====
// C[M,Nc] = A[M,K](lda) @ W[Nc,K]^T.  BM=128, BN=128, BK=32.
// MODE 0: plain store. MODE 1: softplus(v + p0[c]).
#define SA 36
#define TILE_U (128*SA)          // uint32 per tile
#define GEMM_DSMEM (2*2*TILE_U*4) // 2 buffers x (A+B) x bytes

__device__ __forceinline__ uint32_t f2tf(float f) {
    uint32_t u;
    asm("cvt.rna.tf32.f32 %0, %1;" : "=r"(u) : "f"(f));
    return u;
}

__device__ __forceinline__ void mma_tf32(float* d, const uint32_t* a, const uint32_t* b) {
    asm volatile(
        "mma.sync.aligned.m16n8k8.row.col.f32.tf32.tf32.f32 "
        "{%0,%1,%2,%3}, {%4,%5,%6,%7}, {%8,%9}, {%0,%1,%2,%3};"
        : "+f"(d[0]), "+f"(d[1]), "+f"(d[2]), "+f"(d[3])
        : "r"(a[0]), "r"(a[1]), "r"(a[2]), "r"(a[3]), "r"(b[0]), "r"(b[1]));
}

template<int MODE>
__global__ void __launch_bounds__(256) gemm_tc(
    const float* __restrict__ A, int lda,
    const float* __restrict__ W,
    float* __restrict__ C, int Nc, int K,
    const float* __restrict__ p0)
{
    extern __shared__ uint32_t dsm[];

    const int bm = blockIdx.y * 128;
    const int bn = blockIdx.x * 128;
    const int t  = threadIdx.x;
    const int wid  = t >> 5;
    const int lane = t & 31;
    const int qr = lane >> 2;
    const int qc = lane & 3;
    const int warp_m = wid & 3;
    const int warp_n = wid >> 2;

    float acc[2][8][4];
    #pragma unroll
    for (int mt = 0; mt < 2; mt++)
        #pragma unroll
        for (int nt = 0; nt < 8; nt++)
            #pragma unroll
            for (int q = 0; q < 4; q++) acc[mt][nt][q] = 0.f;

    const int NC = (K + 31) / 32;

    float4 aReg[4], bReg[4];
    const float4 z4 = make_float4(0.f, 0.f, 0.f, 0.f);

    // stage chunk 0 into regs
    #pragma unroll
    for (int i = 0; i < 4; i++) {
        int idx = t + i*256;
        int r = idx >> 3;
        int c4 = (idx & 7) * 4;
        aReg[i] = (c4 < K) ? *(const float4*)&A[(size_t)(bm + r)*lda + c4] : z4;
        int j = bn + r;
        bReg[i] = (j < Nc && c4 < K) ? *(const float4*)&W[(size_t)j*K + c4] : z4;
    }

    for (int ch = 0; ch < NC; ch++) {
        const int buf = ch & 1;
        uint32_t* As = dsm + buf * 2 * TILE_U;
        uint32_t* Bs = As + TILE_U;
        // store staged regs (chunk ch) into buffer buf
        #pragma unroll
        for (int i = 0; i < 4; i++) {
            int idx = t + i*256;
            int r = idx >> 3;
            int c4 = (idx & 7) * 4;
            uint4 ua = make_uint4(f2tf(aReg[i].x), f2tf(aReg[i].y), f2tf(aReg[i].z), f2tf(aReg[i].w));
            uint4 ub = make_uint4(f2tf(bReg[i].x), f2tf(bReg[i].y), f2tf(bReg[i].z), f2tf(bReg[i].w));
            *(uint4*)&As[r*SA + c4] = ua;
            *(uint4*)&Bs[r*SA + c4] = ub;
        }
        __syncthreads();

        // prefetch chunk ch+1 into regs (hidden behind MMA)
        if (ch + 1 < NC) {
            const int k0 = (ch + 1) * 32;
            #pragma unroll
            for (int i = 0; i < 4; i++) {
                int idx = t + i*256;
                int r = idx >> 3;
                int c4 = (idx & 7) * 4;
                aReg[i] = (k0 + c4 < K) ? *(const float4*)&A[(size_t)(bm + r)*lda + k0 + c4] : z4;
                int j = bn + r;
                bReg[i] = (j < Nc && k0 + c4 < K) ? *(const float4*)&W[(size_t)j*K + k0 + c4] : z4;
            }
        }

        #pragma unroll
        for (int ks = 0; ks < 4; ks++) {
            const int k0 = ks * 8;
            uint32_t afr[2][4];
            #pragma unroll
            for (int mt = 0; mt < 2; mt++) {
                int r0 = warp_m*32 + mt*16 + qr;
                afr[mt][0] = As[r0*SA + k0 + qc];
                afr[mt][1] = As[(r0+8)*SA + k0 + qc];
                afr[mt][2] = As[r0*SA + k0 + qc + 4];
                afr[mt][3] = As[(r0+8)*SA + k0 + qc + 4];
            }
            uint32_t bfr[8][2];
            #pragma unroll
            for (int nt = 0; nt < 8; nt++) {
                int n = warp_n*64 + nt*8 + qr;
                bfr[nt][0] = Bs[n*SA + k0 + qc];
                bfr[nt][1] = Bs[n*SA + k0 + qc + 4];
            }
            #pragma unroll
            for (int mt = 0; mt < 2; mt++)
                #pragma unroll
                for (int nt = 0; nt < 8; nt++)
                    mma_tf32(acc[mt][nt], afr[mt], bfr[nt]);
        }
        // no second barrier: next iteration writes the OTHER buffer; the
        // iteration-(ch+1) barrier orders its reads/writes correctly.
    }

    if (MODE == 0) {
        #pragma unroll
        for (int mt = 0; mt < 2; mt++) {
            int r0 = bm + warp_m*32 + mt*16 + qr;
            #pragma unroll
            for (int nt = 0; nt < 8; nt++) {
                int c = bn + warp_n*64 + nt*8 + qc*2;
                if (c < Nc) {
                    *(float2*)&C[(size_t)r0*Nc + c]     = make_float2(acc[mt][nt][0], acc[mt][nt][1]);
                    *(float2*)&C[(size_t)(r0+8)*Nc + c] = make_float2(acc[mt][nt][2], acc[mt][nt][3]);
                }
            }
        }
    } else {
        #pragma unroll
        for (int mt = 0; mt < 2; mt++) {
            int r0 = bm + warp_m*32 + mt*16 + qr;
            #pragma unroll
            for (int nt = 0; nt < 8; nt++) {
                int c = bn + warp_n*64 + nt*8 + qc*2;
                if (c < Nc) {
                    float b0 = p0[c], b1 = p0[c+1];
                    float v;
                    v = acc[mt][nt][0] + b0; v = (v > 20.f) ? v : log1pf(__expf(v));
                    C[(size_t)r0*Nc + c] = v;
                    v = acc[mt][nt][1] + b1; v = (v > 20.f) ? v : log1pf(__expf(v));
                    C[(size_t)r0*Nc + c + 1] = v;
                    v = acc[mt][nt][2] + b0; v = (v > 20.f) ? v : log1pf(__expf(v));
                    C[(size_t)(r0+8)*Nc + c] = v;
                    v = acc[mt][nt][3] + b1; v = (v > 20.f) ? v : log1pf(__expf(v));
                    C[(size_t)(r0+8)*Nc + c + 1] = v;
                }
            }
        }
    }
}

// ---------------- BatchNorm stats (grid.x = 256 row slices) ----------------
__global__ void bn_stats(const float* __restrict__ X, int M, int C,
                         float* __restrict__ sum, float* __restrict__ sq)
{
    int c = blockIdx.y * blockDim.x + threadIdx.x;
    if (c >= C) return;
    int rows = M / gridDim.x;
    int r0 = blockIdx.x * rows;
    float s = 0.f, ss = 0.f;
    for (int r = r0; r < r0 + rows; r++) {
        float v = X[(size_t)r*C + c];
        s += v; ss += v*v;
    }
    atomicAdd(&sum[c], s);
    atomicAdd(&sq[c],  ss);
}

__global__ void bn_silu(const float* __restrict__ X, float* __restrict__ Y,
                        const float* __restrict__ sum, const float* __restrict__ sq,
                        const float* __restrict__ g, const float* __restrict__ b,
                        int M, int C)
{
    int idx = blockIdx.x * blockDim.x + threadIdx.x;
    if (idx >= M*C) return;
    int c = idx % C;
    float mean = sum[c] / (float)M;
    float var  = sq[c] / (float)M - mean*mean;
    float v = (X[idx] - mean) * rsqrtf(var + EPSq) * g[c] + b[c];
    Y[idx] = v / (1.f + __expf(-v));
}

// ---------------- depthwise conv K=5, same padding ----------------
__global__ void dwconv5(const float* __restrict__ X, const float* __restrict__ w,
                        float* __restrict__ Y)
{
    int idx = blockIdx.x * blockDim.x + threadIdx.x;
    if (idx >= Nq*HIDq) return;
    int c  = idx % HIDq;
    int l  = (idx / HIDq) % Lq;
    int bb = idx / (HIDq*Lq);
    const float* xb = X + (size_t)bb*Lq*HIDq;
    float acc = 0.f;
    #pragma unroll
    for (int k = 0; k < 5; k++) {
        int ls = l - 2 + k;
        if (ls >= 0 && ls < Lq) acc += xb[(size_t)ls*HIDq + c] * w[c*5 + k];
    }
    Y[idx] = acc;
}

// ---------------- bn_add + LN stats + LN apply, fused ----------------
__global__ void __launch_bounds__(256) bn_add_ln(
    const float* __restrict__ E, const float* __restrict__ X,
    const float* __restrict__ sum3, const float* __restrict__ sq3,
    const float* __restrict__ exg, const float* __restrict__ exb,
    const float* __restrict__ lng, const float* __restrict__ lnb,
    float* __restrict__ X1, float* __restrict__ XN,
    float* __restrict__ rm, float* __restrict__ rs)
{
    const int row = blockIdx.x;
    const int tid = threadIdx.x;
    float vloc[3];
    float s = 0.f, ss = 0.f;
    #pragma unroll
    for (int j = 0; j < 3; j++) {
        int c = tid + j*256;
        float mean = sum3[c] / (float)Nq;
        float var  = sq3[c] / (float)Nq - mean*mean;
        float ga = rsqrtf(var + EPSq) * exg[c];
        float be = exb[c] - mean*ga;
        float v = X[(size_t)row*Dq + c] + E[(size_t)row*Dq + c]*ga + be;
        vloc[j] = v;
        s += v; ss += v*v;
    }
    __shared__ float sh1[8], sh2[8], bcast[2];
    for (int o = 16; o; o >>= 1) {
        s  += __shfl_down_sync(0xffffffffu, s, o);
        ss += __shfl_down_sync(0xffffffffu, ss, o);
    }
    int lane = tid & 31, warp = tid >> 5;
    if (lane == 0) { sh1[warp] = s; sh2[warp] = ss; }
    __syncthreads();
    if (tid == 0) {
        s = 0.f; ss = 0.f;
        #pragma unroll
        for (int wv = 0; wv < 8; wv++) { s += sh1[wv]; ss += sh2[wv]; }
        float m = s / (float)Dq;
        float v = ss / (float)Dq - m*m;
        float r = rsqrtf(v + EPSq);
        bcast[0] = m; bcast[1] = r;
        rm[row] = m; rs[row] = r;
    }
    __syncthreads();
    float m = bcast[0], r = bcast[1];
    #pragma unroll
    for (int j = 0; j < 3; j++) {
        int c = tid + j*256;
        X1[(size_t)row*Dq + c] = vloc[j];
        XN[(size_t)row*Dq + c] = (vloc[j] - m) * r * lng[c] + lnb[c];
    }
}

// ---------------- combine + LN stats, fused ----------------
__global__ void __launch_bounds__(256) combine_ln(
    const float* __restrict__ X, const float* __restrict__ X1,
    const float* __restrict__ MO, const float* __restrict__ GL,
    const float* __restrict__ gb,
    float* __restrict__ XF, float* __restrict__ rm2, float* __restrict__ rs2)
{
    const int row = blockIdx.x;
    const int tid = threadIdx.x;
    float vloc[3];
    float s = 0.f, ss = 0.f;
    #pragma unroll
    for (int j = 0; j < 3; j++) {
        int c = tid + j*256;
        size_t i = (size_t)row*Dq + c;
        float gate = 1.f / (1.f + __expf(-(GL[i] + gb[c])));
        float v = X1[i] + MO[i]*gate + X[i];
        vloc[j] = v;
        s += v; ss += v*v;
    }
    __shared__ float sh1[8], sh2[8];
    for (int o = 16; o; o >>= 1) {
        s  += __shfl_down_sync(0xffffffffu, s, o);
        ss += __shfl_down_sync(0xffffffffu, ss, o);
    }
    int lane = tid & 31, warp = tid >> 5;
    if (lane == 0) { sh1[warp] = s; sh2[warp] = ss; }
    __syncthreads();
    if (tid == 0) {
        s = 0.f; ss = 0.f;
        #pragma unroll
        for (int wv = 0; wv < 8; wv++) { s += sh1[wv]; ss += sh2[wv]; }
        float m = s / (float)Dq;
        float v = ss / (float)Dq - m*m;
        rm2[row] = m;
        rs2[row] = rsqrtf(v + EPSq);
    }
    #pragma unroll
    for (int j = 0; j < 3; j++) {
        int c = tid + j*256;
        XF[(size_t)row*Dq + c] = vloc[j];
    }
}

// ---------------- causal depthwise conv K=4 + bias + silu ----------------
__global__ void conv_causal_silu(const float* __restrict__ XZ, const float* __restrict__ w,
                                 const float* __restrict__ bias, float* __restrict__ Y)
{
    int idx = blockIdx.x * blockDim.x + threadIdx.x;
    if (idx >= Nq*DIq) return;
    int c  = idx % DIq;
    int l  = (idx / DIq) % Lq;
    int bb = idx / (DIq*Lq);
    float acc = bias[c];
    #pragma unroll
    for (int k = 0; k < 4; k++) {
        int ls = l - 3 + k;
        if (ls >= 0) acc += XZ[(size_t)(bb*Lq + ls)*(2*DIq) + c] * w[c*4 + k];
    }
    Y[idx] = acc / (1.f + __expf(-acc));
}

// feat_attr[b,c] = max_l LN(x1)[b,l,c]
__global__ void attr_max(const float* __restrict__ X, const float* __restrict__ mean,
                         const float* __restrict__ rstd, const float* __restrict__ g,
                         const float* __restrict__ b, float* __restrict__ out)
{
    int c  = blockIdx.y * blockDim.x + threadIdx.x;
    int bb = blockIdx.x;
    float gm = g[c], gb = b[c];
    float mx = -3.4e38f;
    for (int l = 0; l < Lq; l++) {
        int row = bb*Lq + l;
        float v = (X[(size_t)row*Dq + c] - mean[row]) * rstd[row] * gm + gb;
        mx = fmaxf(mx, v);
    }
    out[bb*Dq + c] = mx;
}

// ---------------- selective scan (128-thread blocks, prefetched) ----------------
__global__ void __launch_bounds__(128) scan_k(
    const float* __restrict__ delta, const float* __restrict__ u,
    const float* __restrict__ dbc,   const float* __restrict__ xz,
    const float* __restrict__ A_log, const float* __restrict__ Dp,
    float* __restrict__ y)
{
    __shared__ float Bs[128][DSq];
    __shared__ float Cs[128][DSq];
    const int bb = blockIdx.y;
    const int d  = blockIdx.x * 128 + threadIdx.x;

    float A[DSq], h[DSq];
    #pragma unroll
    for (int s = 0; s < DSq; s++) { A[s] = -expf(A_log[d*DSq + s]); h[s] = 0.f; }
    const float dp = Dp[d];

    for (int c0 = 0; c0 < Lq; c0 += 128) {
        for (int i = threadIdx.x; i < 128*DSq; i += 128) {
            int l = i >> 4, s = i & 15;
            size_t row = (size_t)(bb*Lq + c0 + l);
            Bs[l][s] = dbc[row*80 + DTRq + s];
            Cs[l][s] = dbc[row*80 + DTRq + DSq + s];
        }
        __syncthreads();
        size_t row0 = (size_t)(bb*Lq + c0);
        float dv = delta[row0*DIq + d];
        float uv = u[row0*DIq + d];
        float zv = xz[row0*(2*DIq) + DIq + d];
        for (int l = 0; l < 128; l++) {
            float nd = 0.f, nu = 0.f, nz = 0.f;
            if (l < 127) {
                size_t rn = row0 + l + 1;
                nd = delta[rn*DIq + d];
                nu = u[rn*DIq + d];
                nz = xz[rn*(2*DIq) + DIq + d];
            }
            float du = dv * uv;
            float acc = 0.f;
            #pragma unroll
            for (int s = 0; s < DSq; s++) {
                h[s] = h[s] * __expf(dv * A[s]) + du * Bs[l][s];
                acc  = fmaf(h[s], Cs[l][s], acc);
            }
            float sz = zv / (1.f + __expf(-zv));
            y[(row0 + l)*DIq + d] = (acc + uv*dp) * sz;
            dv = nd; uv = nu; zv = nz;
        }
        __syncthreads();
    }
}

// feat_id[b,c] = mean_l LN(xf)[b,l,c]
__global__ void feat_id_k(const float* __restrict__ X, const float* __restrict__ mean,
                          const float* __restrict__ rstd, const float* __restrict__ g,
                          const float* __restrict__ b, float* __restrict__ fid,
                          float* __restrict__ out)
{
    int c  = blockIdx.y * blockDim.x + threadIdx.x;
    int bb = blockIdx.x;
    float gm = g[c], gb = b[c];
    float s = 0.f;
    for (int l = 0; l < Lq; l++) {
        int row = bb*Lq + l;
        s += (X[(size_t)row*Dq + c] - mean[row]) * rstd[row] * gm + gb;
    }
    float v = s / (float)Lq;
    fid[bb*Dq + c] = v;
    out[bb*Dq + c] = v;
}

__global__ void feat_bn(const float* __restrict__ fid, const float* __restrict__ g,
                        const float* __restrict__ b, float* __restrict__ out)
{
    int c = blockIdx.x * blockDim.x + threadIdx.x;
    if (c >= Dq) return;
    float s = 0.f, ss = 0.f;
    for (int bb = 0; bb < Bq; bb++) {
        float v = fid[bb*Dq + c]; s += v; ss += v*v;
    }
    float m = s / (float)Bq;
    float var = ss / (float)Bq - m*m;
    float rs = rsqrtf(var + EPSq);
    for (int bb = 0; bb < Bq; bb++)
        out[bb*Dq + c] = (fid[bb*Dq + c] - m) * rs * g[c] + b[c];
}

// ---------------- host ----------------
#define GETSYM(p, s) { void* _t; cudaGetSymbolAddress(&_t, s); p = (float*)_t; }

extern "C" void kernel_launch(void* const* d_in, const int* in_sizes, int n_in,
                              void* d_out, int out_size)
{
    const float* x        = (const float*)d_in[0];
    const float* sq_w     = (const float*)d_in[1];
    const float* sq_bn_g  = (const float*)d_in[2];
    const float* sq_bn_b  = (const float*)d_in[3];
    const float* dw_w     = (const float*)d_in[4];
    const float* dw_bn_g  = (const float*)d_in[5];
    const float* dw_bn_b  = (const float*)d_in[6];
    const float* ex_w     = (const float*)d_in[7];
    const float* ex_bn_g  = (const float*)d_in[8];
    const float* ex_bn_b  = (const float*)d_in[9];
    const float* attr_g   = (const float*)d_in[10];
    const float* attr_b   = (const float*)d_in[11];
    const float* mnorm_g  = (const float*)d_in[12];
    const float* mnorm_b  = (const float*)d_in[13];
    const float* in_proj_w= (const float*)d_in[14];
    const float* conv_w   = (const float*)d_in[15];
    const float* conv_b   = (const float*)d_in[16];
    const float* xproj_w  = (const float*)d_in[17];
    const float* dtproj_w = (const float*)d_in[18];
    const float* dtproj_b = (const float*)d_in[19];
    const float* A_log    = (const float*)d_in[20];
    const float* D_param  = (const float*)d_in[21];
    const float* out_proj_w = (const float*)d_in[22];
    const float* gate_w   = (const float*)d_in[23];
    const float* gate_b   = (const float*)d_in[24];
    const float* idn_g    = (const float*)d_in[25];
    const float* idn_b    = (const float*)d_in[26];
    const float* idbn_g   = (const float*)d_in[27];
    const float* idbn_b   = (const float*)d_in[28];
    float* out = (float*)d_out;

    float *h0,*tmpH,*h2,*e,*x1,*xn,*xz,*xm2,*dbc,*del,*y,*mo,*gl,*xf;
    float *rm,*rs,*rm2,*rs2,*fid,*stats;
    GETSYM(h0, g_h0);   GETSYM(tmpH, g_tmpH); GETSYM(h2, g_h2);
    GETSYM(e, g_e);     GETSYM(x1, g_x1);     GETSYM(xn, g_xn);
    GETSYM(xz, g_xz);   GETSYM(xm2, g_xm2);   GETSYM(dbc, g_dbc);
    GETSYM(del, g_del); GETSYM(y, g_y);       GETSYM(mo, g_mo);
    GETSYM(gl, g_gl);   GETSYM(xf, g_xf);
    GETSYM(rm, g_rm);   GETSYM(rs, g_rs);     GETSYM(rm2, g_rm2); GETSYM(rs2, g_rs2);
    GETSYM(fid, g_fid); GETSYM(stats, g_stats);

    float* sum1 = stats + ST_SUM1;
    float* sq1  = stats + ST_SQ1;
    float* sum2 = stats + ST_SUM2;
    float* sq2  = stats + ST_SQ2;
    float* sum3 = stats + ST_SUM3;
    float* sq3  = stats + ST_SQ3;

    // one-time side stream + events (host objects; not device memory)
    static cudaStream_t s1 = 0;
    static cudaEvent_t evFork = 0, evJoin = 0;
    static int smemSet = 0;
    if (!s1) {
        cudaStreamCreateWithFlags(&s1, cudaStreamNonBlocking);
        cudaEventCreateWithFlags(&evFork, cudaEventDisableTiming);
        cudaEventCreateWithFlags(&evJoin, cudaEventDisableTiming);
    }
    if (!smemSet) {
        cudaFuncSetAttribute(gemm_tc<0>, cudaFuncAttributeMaxDynamicSharedMemorySize, GEMM_DSMEM);
        cudaFuncSetAttribute(gemm_tc<1>, cudaFuncAttributeMaxDynamicSharedMemorySize, GEMM_DSMEM);
        smemSet = 1;
    }

    const int T = 256;
    dim3 gHID((Nq*HIDq + T-1)/T), gDI((Nq*DIq + T-1)/T);

    cudaMemsetAsync(stats, 0, ST_TOTAL*sizeof(float));

    // 1) squeeze GEMM + BN+SiLU
    gemm_tc<0><<<dim3(2, Nq/128), 256, GEMM_DSMEM>>>(x, Dq, sq_w, h0, HIDq, Dq, 0);
    bn_stats<<<dim3(256,1), T>>>(h0, Nq, HIDq, sum1, sq1);
    bn_silu<<<gHID, T>>>(h0, h0, sum1, sq1, sq_bn_g, sq_bn_b, Nq, HIDq);

    // 2) dwconv K=5 + BN+SiLU
    dwconv5<<<gHID, T>>>(h0, dw_w, tmpH);
    bn_stats<<<dim3(256,1), T>>>(tmpH, Nq, HIDq, sum2, sq2);
    bn_silu<<<gHID, T>>>(tmpH, h2, sum2, sq2, dw_bn_g, dw_bn_b, Nq, HIDq);

    // 3) excite GEMM + fused bn_add + LN
    gemm_tc<0><<<dim3(6, Nq/128), 256, GEMM_DSMEM>>>(h2, HIDq, ex_w, e, Dq, HIDq, 0);
    bn_stats<<<dim3(256,3), T>>>(e, Nq, Dq, sum3, sq3);
    bn_add_ln<<<Nq, T>>>(e, x, sum3, sq3, ex_bn_g, ex_bn_b, mnorm_g, mnorm_b,
                         x1, xn, rm, rs);

    // fork: side stream does feat_attr + gate GEMM while main stream runs the
    // mamba chain (in_proj -> conv -> xproj -> dtproj -> scan -> out_proj)
    cudaEventRecord(evFork, 0);
    cudaStreamWaitEvent(s1, evFork, 0);
    attr_max<<<dim3(Bq,3), T, 0, s1>>>(x1, rm, rs, attr_g, attr_b, out);
    gemm_tc<0><<<dim3(6, Nq/128), 256, GEMM_DSMEM, s1>>>(xn, Dq, gate_w, gl, Dq, Dq, 0);
    cudaEventRecord(evJoin, s1);

    // 5) Mamba in_proj
    gemm_tc<0><<<dim3(24, Nq/128), 256, GEMM_DSMEM>>>(xn, Dq, in_proj_w, xz, 2*DIq, Dq, 0);

    // 6) causal conv + silu
    conv_causal_silu<<<gDI, T>>>(xz, conv_w, conv_b, xm2);

    // 7) x_proj; dt_proj (+softplus epilogue)
    gemm_tc<0><<<dim3(1, Nq/128), 256, GEMM_DSMEM>>>(xm2, DIq, xproj_w, dbc, 80, DIq, 0);
    gemm_tc<1><<<dim3(12, Nq/128), 256, GEMM_DSMEM>>>(dbc, 80, dtproj_w, del, DIq, DTRq, dtproj_b);

    // 8) selective scan
    scan_k<<<dim3(DIq/128, Bq), 128>>>(del, xm2, dbc, xz, A_log, D_param, y);

    // 9) out_proj; join side stream; fused combine + LN stats
    gemm_tc<0><<<dim3(6, Nq/128), 256, GEMM_DSMEM>>>(y, DIq, out_proj_w, mo, Dq, DIq, 0);
    cudaStreamWaitEvent(0, evJoin, 0);
    combine_ln<<<Nq, T>>>(x, x1, mo, gl, gate_b, xf, rm2, rs2);

    // 10) feat_id + feat_id_bn
    feat_id_k<<<dim3(Bq,3), T>>>(xf, rm2, rs2, idn_g, idn_b, fid, out + Bq*Dq);
    feat_bn<<<3, T>>>(fid, idbn_g, idbn_b, out + 2*Bq*Dq);
}

// round 9
// speedup vs baseline: 2.0418x; 1.0105x over previous
#include <cuda_runtime.h>
#include <math.h>
#include <stdint.h>

#define Bq    32
#define Lq    512
#define Dq    768
#define HIDq  192
#define DIq   1536
#define DSq   16
#define DTRq  48
#define Nq    (Bq*Lq)        // 16384
#define EPSq  1e-5f

// ---------------- scratch ----------------
__device__ __align__(256) float g_h0  [Nq*HIDq];
__device__ __align__(256) float g_tmpH[Nq*HIDq];
__device__ __align__(256) float g_h2  [Nq*HIDq];
__device__ __align__(256) float g_e   [Nq*Dq];
__device__ __align__(256) float g_x1  [Nq*Dq];
__device__ __align__(256) float g_xn  [Nq*Dq];
__device__ __align__(256) float g_xz  [Nq*2*DIq];
__device__ __align__(256) float g_xm2 [Nq*DIq];
__device__ __align__(256) float g_dbc [Nq*80];
__device__ __align__(256) float g_del [Nq*DIq];
__device__ __align__(256) float g_y   [Nq*DIq];
__device__ __align__(256) float g_mo  [Nq*Dq];
__device__ __align__(256) float g_gl  [Nq*Dq];
__device__ __align__(256) float g_xf  [Nq*Dq];
__device__ __align__(256) float g_rm  [Nq];
__device__ __align__(256) float g_rs  [Nq];
__device__ __align__(256) float g_rm2 [Nq];
__device__ __align__(256) float g_rs2 [Nq];
__device__ __align__(256) float g_fid [Bq*Dq];
#define ST_SUM1   0
#define ST_SQ1    (ST_SUM1+192)
#define ST_SUM2   (ST_SQ1+192)
#define ST_SQ2    (ST_SUM2+192)
#define ST_SUM3   (ST_SQ2+192)
#define ST_SQ3    (ST_SUM3+768)
#define ST_TOTAL  (ST_SQ3+768)
__device__ __align__(256) float g_stats[ST_TOTAL];

// ================= TF32 mma.sync GEMM (double-buffered smem, 1 sync/chunk) =====
// C[M,Nc] = A[M,K](lda) @ W[Nc,K]^T, C row stride = ldc.
// MODE 0: plain store. MODE 1: softplus(v + p0[c]).
#define SA 36
#define TILE_U (128*SA)
#define GEMM_DSMEM (2*2*TILE_U*4)

__device__ __forceinline__ uint32_t f2tf(float f) {
    uint32_t u;
    asm("cvt.rna.tf32.f32 %0, %1;" : "=r"(u) : "f"(f));
    return u;
}

__device__ __forceinline__ void mma_tf32(float* d, const uint32_t* a, const uint32_t* b) {
    asm volatile(
        "mma.sync.aligned.m16n8k8.row.col.f32.tf32.tf32.f32 "
        "{%0,%1,%2,%3}, {%4,%5,%6,%7}, {%8,%9}, {%0,%1,%2,%3};"
        : "+f"(d[0]), "+f"(d[1]), "+f"(d[2]), "+f"(d[3])
        : "r"(a[0]), "r"(a[1]), "r"(a[2]), "r"(a[3]), "r"(b[0]), "r"(b[1]));
}

template<int MODE>
__global__ void __launch_bounds__(256) gemm_tc(
    const float* __restrict__ A, int lda,
    const float* __restrict__ W,
    float* __restrict__ C, int Nc, int ldc, int K,
    const float* __restrict__ p0)
{
    extern __shared__ uint32_t dsm[];

    const int bm = blockIdx.y * 128;
    const int bn = blockIdx.x * 128;
    const int t  = threadIdx.x;
    const int wid  = t >> 5;
    const int lane = t & 31;
    const int qr = lane >> 2;
    const int qc = lane & 3;
    const int warp_m = wid & 3;
    const int warp_n = wid >> 2;

    float acc[2][8][4];
    #pragma unroll
    for (int mt = 0; mt < 2; mt++)
        #pragma unroll
        for (int nt = 0; nt < 8; nt++)
            #pragma unroll
            for (int q = 0; q < 4; q++) acc[mt][nt][q] = 0.f;

    const int NC = (K + 31) / 32;

    float4 aReg[4], bReg[4];
    const float4 z4 = make_float4(0.f, 0.f, 0.f, 0.f);

    #pragma unroll
    for (int i = 0; i < 4; i++) {
        int idx = t + i*256;
        int r = idx >> 3;
        int c4 = (idx & 7) * 4;
        aReg[i] = (c4 < K) ? *(const float4*)&A[(size_t)(bm + r)*lda + c4] : z4;
        int j = bn + r;
        bReg[i] = (j < Nc && c4 < K) ? *(const float4*)&W[(size_t)j*K + c4] : z4;
    }

    for (int ch = 0; ch < NC; ch++) {
        const int buf = ch & 1;
        uint32_t* As = dsm + buf * 2 * TILE_U;
        uint32_t* Bs = As + TILE_U;
        #pragma unroll
        for (int i = 0; i < 4; i++) {
            int idx = t + i*256;
            int r = idx >> 3;
            int c4 = (idx & 7) * 4;
            uint4 ua = make_uint4(f2tf(aReg[i].x), f2tf(aReg[i].y), f2tf(aReg[i].z), f2tf(aReg[i].w));
            uint4 ub = make_uint4(f2tf(bReg[i].x), f2tf(bReg[i].y), f2tf(bReg[i].z), f2tf(bReg[i].w));
            *(uint4*)&As[r*SA + c4] = ua;
            *(uint4*)&Bs[r*SA + c4] = ub;
        }
        __syncthreads();

        if (ch + 1 < NC) {
            const int k0 = (ch + 1) * 32;
            #pragma unroll
            for (int i = 0; i < 4; i++) {
                int idx = t + i*256;
                int r = idx >> 3;
                int c4 = (idx & 7) * 4;
                aReg[i] = (k0 + c4 < K) ? *(const float4*)&A[(size_t)(bm + r)*lda + k0 + c4] : z4;
                int j = bn + r;
                bReg[i] = (j < Nc && k0 + c4 < K) ? *(const float4*)&W[(size_t)j*K + k0 + c4] : z4;
            }
        }

        #pragma unroll
        for (int ks = 0; ks < 4; ks++) {
            const int k0 = ks * 8;
            uint32_t afr[2][4];
            #pragma unroll
            for (int mt = 0; mt < 2; mt++) {
                int r0 = warp_m*32 + mt*16 + qr;
                afr[mt][0] = As[r0*SA + k0 + qc];
                afr[mt][1] = As[(r0+8)*SA + k0 + qc];
                afr[mt][2] = As[r0*SA + k0 + qc + 4];
                afr[mt][3] = As[(r0+8)*SA + k0 + qc + 4];
            }
            uint32_t bfr[8][2];
            #pragma unroll
            for (int nt = 0; nt < 8; nt++) {
                int n = warp_n*64 + nt*8 + qr;
                bfr[nt][0] = Bs[n*SA + k0 + qc];
                bfr[nt][1] = Bs[n*SA + k0 + qc + 4];
            }
            #pragma unroll
            for (int mt = 0; mt < 2; mt++)
                #pragma unroll
                for (int nt = 0; nt < 8; nt++)
                    mma_tf32(acc[mt][nt], afr[mt], bfr[nt]);
        }
    }

    if (MODE == 0) {
        #pragma unroll
        for (int mt = 0; mt < 2; mt++) {
            int r0 = bm + warp_m*32 + mt*16 + qr;
            #pragma unroll
            for (int nt = 0; nt < 8; nt++) {
                int c = bn + warp_n*64 + nt*8 + qc*2;
                if (c < Nc) {
                    *(float2*)&C[(size_t)r0*ldc + c]     = make_float2(acc[mt][nt][0], acc[mt][nt][1]);
                    *(float2*)&C[(size_t)(r0+8)*ldc + c] = make_float2(acc[mt][nt][2], acc[mt][nt][3]);
                }
            }
        }
    } else {
        #pragma unroll
        for (int mt = 0; mt < 2; mt++) {
            int r0 = bm + warp_m*32 + mt*16 + qr;
            #pragma unroll
            for (int nt = 0; nt < 8; nt++) {
                int c = bn + warp_n*64 + nt*8 + qc*2;
                if (c < Nc) {
                    float b0 = p0[c], b1 = p0[c+1];
                    float v;
                    v = acc[mt][nt][0] + b0; v = (v > 20.f) ? v : log1pf(__expf(v));
                    C[(size_t)r0*ldc + c] = v;
                    v = acc[mt][nt][1] + b1; v = (v > 20.f) ? v : log1pf(__expf(v));
                    C[(size_t)r0*ldc + c + 1] = v;
                    v = acc[mt][nt][2] + b0; v = (v > 20.f) ? v : log1pf(__expf(v));
                    C[(size_t)(r0+8)*ldc + c] = v;
                    v = acc[mt][nt][3] + b1; v = (v > 20.f) ? v : log1pf(__expf(v));
                    C[(size_t)(r0+8)*ldc + c + 1] = v;
                }
            }
        }
    }
}

// ---------------- BatchNorm stats ----------------
__global__ void bn_stats(const float* __restrict__ X, int M, int C,
                         float* __restrict__ sum, float* __restrict__ sq)
{
    int c = blockIdx.y * blockDim.x + threadIdx.x;
    if (c >= C) return;
    int rows = M / gridDim.x;
    int r0 = blockIdx.x * rows;
    float s = 0.f, ss = 0.f;
    for (int r = r0; r < r0 + rows; r++) {
        float v = X[(size_t)r*C + c];
        s += v; ss += v*v;
    }
    atomicAdd(&sum[c], s);
    atomicAdd(&sq[c],  ss);
}

__global__ void bn_silu(const float* __restrict__ X, float* __restrict__ Y,
                        const float* __restrict__ sum, const float* __restrict__ sq,
                        const float* __restrict__ g, const float* __restrict__ b,
                        int M, int C)
{
    int idx = blockIdx.x * blockDim.x + threadIdx.x;
    if (idx >= M*C) return;
    int c = idx % C;
    float mean = sum[c] / (float)M;
    float var  = sq[c] / (float)M - mean*mean;
    float v = (X[idx] - mean) * rsqrtf(var + EPSq) * g[c] + b[c];
    Y[idx] = v / (1.f + __expf(-v));
}

// ---------------- depthwise conv K=5 ----------------
__global__ void dwconv5(const float* __restrict__ X, const float* __restrict__ w,
                        float* __restrict__ Y)
{
    int idx = blockIdx.x * blockDim.x + threadIdx.x;
    if (idx >= Nq*HIDq) return;
    int c  = idx % HIDq;
    int l  = (idx / HIDq) % Lq;
    int bb = idx / (HIDq*Lq);
    const float* xb = X + (size_t)bb*Lq*HIDq;
    float acc = 0.f;
    #pragma unroll
    for (int k = 0; k < 5; k++) {
        int ls = l - 2 + k;
        if (ls >= 0 && ls < Lq) acc += xb[(size_t)ls*HIDq + c] * w[c*5 + k];
    }
    Y[idx] = acc;
}

// ---------------- bn_add + LN, fused ----------------
__global__ void __launch_bounds__(256) bn_add_ln(
    const float* __restrict__ E, const float* __restrict__ X,
    const float* __restrict__ sum3, const float* __restrict__ sq3,
    const float* __restrict__ exg, const float* __restrict__ exb,
    const float* __restrict__ lng, const float* __restrict__ lnb,
    float* __restrict__ X1, float* __restrict__ XN,
    float* __restrict__ rm, float* __restrict__ rs)
{
    const int row = blockIdx.x;
    const int tid = threadIdx.x;
    float vloc[3];
    float s = 0.f, ss = 0.f;
    #pragma unroll
    for (int j = 0; j < 3; j++) {
        int c = tid + j*256;
        float mean = sum3[c] / (float)Nq;
        float var  = sq3[c] / (float)Nq - mean*mean;
        float ga = rsqrtf(var + EPSq) * exg[c];
        float be = exb[c] - mean*ga;
        float v = X[(size_t)row*Dq + c] + E[(size_t)row*Dq + c]*ga + be;
        vloc[j] = v;
        s += v; ss += v*v;
    }
    __shared__ float sh1[8], sh2[8], bcast[2];
    for (int o = 16; o; o >>= 1) {
        s  += __shfl_down_sync(0xffffffffu, s, o);
        ss += __shfl_down_sync(0xffffffffu, ss, o);
    }
    int lane = tid & 31, warp = tid >> 5;
    if (lane == 0) { sh1[warp] = s; sh2[warp] = ss; }
    __syncthreads();
    if (tid == 0) {
        s = 0.f; ss = 0.f;
        #pragma unroll
        for (int wv = 0; wv < 8; wv++) { s += sh1[wv]; ss += sh2[wv]; }
        float m = s / (float)Dq;
        float v = ss / (float)Dq - m*m;
        float r = rsqrtf(v + EPSq);
        bcast[0] = m; bcast[1] = r;
        rm[row] = m; rs[row] = r;
    }
    __syncthreads();
    float m = bcast[0], r = bcast[1];
    #pragma unroll
    for (int j = 0; j < 3; j++) {
        int c = tid + j*256;
        X1[(size_t)row*Dq + c] = vloc[j];
        XN[(size_t)row*Dq + c] = (vloc[j] - m) * r * lng[c] + lnb[c];
    }
}

// ---------------- combine + LN stats, fused ----------------
__global__ void __launch_bounds__(256) combine_ln(
    const float* __restrict__ X, const float* __restrict__ X1,
    const float* __restrict__ MO, const float* __restrict__ GL,
    const float* __restrict__ gb,
    float* __restrict__ XF, float* __restrict__ rm2, float* __restrict__ rs2)
{
    const int row = blockIdx.x;
    const int tid = threadIdx.x;
    float vloc[3];
    float s = 0.f, ss = 0.f;
    #pragma unroll
    for (int j = 0; j < 3; j++) {
        int c = tid + j*256;
        size_t i = (size_t)row*Dq + c;
        float gate = 1.f / (1.f + __expf(-(GL[i] + gb[c])));
        float v = X1[i] + MO[i]*gate + X[i];
        vloc[j] = v;
        s += v; ss += v*v;
    }
    __shared__ float sh1[8], sh2[8];
    for (int o = 16; o; o >>= 1) {
        s  += __shfl_down_sync(0xffffffffu, s, o);
        ss += __shfl_down_sync(0xffffffffu, ss, o);
    }
    int lane = tid & 31, warp = tid >> 5;
    if (lane == 0) { sh1[warp] = s; sh2[warp] = ss; }
    __syncthreads();
    if (tid == 0) {
        s = 0.f; ss = 0.f;
        #pragma unroll
        for (int wv = 0; wv < 8; wv++) { s += sh1[wv]; ss += sh2[wv]; }
        float m = s / (float)Dq;
        float v = ss / (float)Dq - m*m;
        rm2[row] = m;
        rs2[row] = rsqrtf(v + EPSq);
    }
    #pragma unroll
    for (int j = 0; j < 3; j++) {
        int c = tid + j*256;
        XF[(size_t)row*Dq + c] = vloc[j];
    }
}

// ---------------- causal depthwise conv K=4 + bias + silu ----------------
__global__ void conv_causal_silu(const float* __restrict__ XZ, const float* __restrict__ w,
                                 const float* __restrict__ bias, float* __restrict__ Y)
{
    int idx = blockIdx.x * blockDim.x + threadIdx.x;
    if (idx >= Nq*DIq) return;
    int c  = idx % DIq;
    int l  = (idx / DIq) % Lq;
    int bb = idx / (DIq*Lq);
    float acc = bias[c];
    #pragma unroll
    for (int k = 0; k < 4; k++) {
        int ls = l - 3 + k;
        if (ls >= 0) acc += XZ[(size_t)(bb*Lq + ls)*(2*DIq) + c] * w[c*4 + k];
    }
    Y[idx] = acc / (1.f + __expf(-acc));
}

// feat_attr
__global__ void attr_max(const float* __restrict__ X, const float* __restrict__ mean,
                         const float* __restrict__ rstd, const float* __restrict__ g,
                         const float* __restrict__ b, float* __restrict__ out)
{
    int c  = blockIdx.y * blockDim.x + threadIdx.x;
    int bb = blockIdx.x;
    float gm = g[c], gb = b[c];
    float mx = -3.4e38f;
    for (int l = 0; l < Lq; l++) {
        int row = bb*Lq + l;
        float v = (X[(size_t)row*Dq + c] - mean[row]) * rstd[row] * gm + gb;
        mx = fmaxf(mx, v);
    }
    out[bb*Dq + c] = mx;
}

// ---------------- selective scan (pow-chain fast path) ----------------
__global__ void __launch_bounds__(128) scan_k(
    const float* __restrict__ delta, const float* __restrict__ u,
    const float* __restrict__ dbc,   const float* __restrict__ xz,
    const float* __restrict__ A_log, const float* __restrict__ Dp,
    float* __restrict__ y)
{
    __shared__ float Bs[128][DSq];
    __shared__ float Cs[128][DSq];
    const int bb = blockIdx.y;
    const int d  = blockIdx.x * 128 + threadIdx.x;

    float A[DSq], h[DSq];
    bool fast = true;
    #pragma unroll
    for (int s = 0; s < DSq; s++) {
        A[s] = -expf(A_log[d*DSq + s]);
        h[s] = 0.f;
        if (fabsf(A[s] + (float)(s+1)) > 1e-3f * (float)(s+1)) fast = false;
    }
    const float dp = Dp[d];

    for (int c0 = 0; c0 < Lq; c0 += 128) {
        for (int i = threadIdx.x; i < 128*DSq; i += 128) {
            int l = i >> 4, s = i & 15;
            size_t row = (size_t)(bb*Lq + c0 + l);
            Bs[l][s] = dbc[row*80 + DTRq + s];
            Cs[l][s] = dbc[row*80 + DTRq + DSq + s];
        }
        __syncthreads();
        size_t row0 = (size_t)(bb*Lq + c0);
        float dv = delta[row0*DIq + d];
        float uv = u[row0*DIq + d];
        float zv = xz[row0*(2*DIq) + DIq + d];
        if (fast) {
            for (int l = 0; l < 128; l++) {
                float nd = 0.f, nu = 0.f, nz = 0.f;
                if (l < 127) {
                    size_t rn = row0 + l + 1;
                    nd = delta[rn*DIq + d];
                    nu = u[rn*DIq + d];
                    nz = xz[rn*(2*DIq) + DIq + d];
                }
                float du = dv * uv;
                float e1 = __expf(-dv);     // exp(dv*A[s]) = e1^(s+1)
                float p = e1;
                float acc = 0.f;
                #pragma unroll
                for (int s = 0; s < DSq; s++) {
                    h[s] = h[s] * p + du * Bs[l][s];
                    acc  = fmaf(h[s], Cs[l][s], acc);
                    p *= e1;
                }
                float sz = zv / (1.f + __expf(-zv));
                y[(row0 + l)*DIq + d] = (acc + uv*dp) * sz;
                dv = nd; uv = nu; zv = nz;
            }
        } else {
            for (int l = 0; l < 128; l++) {
                float nd = 0.f, nu = 0.f, nz = 0.f;
                if (l < 127) {
                    size_t rn = row0 + l + 1;
                    nd = delta[rn*DIq + d];
                    nu = u[rn*DIq + d];
                    nz = xz[rn*(2*DIq) + DIq + d];
                }
                float du = dv * uv;
                float acc = 0.f;
                #pragma unroll
                for (int s = 0; s < DSq; s++) {
                    h[s] = h[s] * __expf(dv * A[s]) + du * Bs[l][s];
                    acc  = fmaf(h[s], Cs[l][s], acc);
                }
                float sz = zv / (1.f + __expf(-zv));
                y[(row0 + l)*DIq + d] = (acc + uv*dp) * sz;
                dv = nd; uv = nu; zv = nz;
            }
        }
        __syncthreads();
    }
}

// feat_id
__global__ void feat_id_k(const float* __restrict__ X, const float* __restrict__ mean,
                          const float* __restrict__ rstd, const float* __restrict__ g,
                          const float* __restrict__ b, float* __restrict__ fid,
                          float* __restrict__ out)
{
    int c  = blockIdx.y * blockDim.x + threadIdx.x;
    int bb = blockIdx.x;
    float gm = g[c], gb = b[c];
    float s = 0.f;
    for (int l = 0; l < Lq; l++) {
        int row = bb*Lq + l;
        s += (X[(size_t)row*Dq + c] - mean[row]) * rstd[row] * gm + gb;
    }
    float v = s / (float)Lq;
    fid[bb*Dq + c] = v;
    out[bb*Dq + c] = v;
}

__global__ void feat_bn(const float* __restrict__ fid, const float* __restrict__ g,
                        const float* __restrict__ b, float* __restrict__ out)
{
    int c = blockIdx.x * blockDim.x + threadIdx.x;
    if (c >= Dq) return;
    float s = 0.f, ss = 0.f;
    for (int bb = 0; bb < Bq; bb++) {
        float v = fid[bb*Dq + c]; s += v; ss += v*v;
    }
    float m = s / (float)Bq;
    float var = ss / (float)Bq - m*m;
    float rs = rsqrtf(var + EPSq);
    for (int bb = 0; bb < Bq; bb++)
        out[bb*Dq + c] = (fid[bb*Dq + c] - m) * rs * g[c] + b[c];
}

// ---------------- host ----------------
#define GETSYM(p, s) { void* _t; cudaGetSymbolAddress(&_t, s); p = (float*)_t; }

extern "C" void kernel_launch(void* const* d_in, const int* in_sizes, int n_in,
                              void* d_out, int out_size)
{
    const float* x        = (const float*)d_in[0];
    const float* sq_w     = (const float*)d_in[1];
    const float* sq_bn_g  = (const float*)d_in[2];
    const float* sq_bn_b  = (const float*)d_in[3];
    const float* dw_w     = (const float*)d_in[4];
    const float* dw_bn_g  = (const float*)d_in[5];
    const float* dw_bn_b  = (const float*)d_in[6];
    const float* ex_w     = (const float*)d_in[7];
    const float* ex_bn_g  = (const float*)d_in[8];
    const float* ex_bn_b  = (const float*)d_in[9];
    const float* attr_g   = (const float*)d_in[10];
    const float* attr_b   = (const float*)d_in[11];
    const float* mnorm_g  = (const float*)d_in[12];
    const float* mnorm_b  = (const float*)d_in[13];
    const float* in_proj_w= (const float*)d_in[14];
    const float* conv_w   = (const float*)d_in[15];
    const float* conv_b   = (const float*)d_in[16];
    const float* xproj_w  = (const float*)d_in[17];
    const float* dtproj_w = (const float*)d_in[18];
    const float* dtproj_b = (const float*)d_in[19];
    const float* A_log    = (const float*)d_in[20];
    const float* D_param  = (const float*)d_in[21];
    const float* out_proj_w = (const float*)d_in[22];
    const float* gate_w   = (const float*)d_in[23];
    const float* gate_b   = (const float*)d_in[24];
    const float* idn_g    = (const float*)d_in[25];
    const float* idn_b    = (const float*)d_in[26];
    const float* idbn_g   = (const float*)d_in[27];
    const float* idbn_b   = (const float*)d_in[28];
    float* out = (float*)d_out;

    float *h0,*tmpH,*h2,*e,*x1,*xn,*xz,*xm2,*dbc,*del,*y,*mo,*gl,*xf;
    float *rm,*rs,*rm2,*rs2,*fid,*stats;
    GETSYM(h0, g_h0);   GETSYM(tmpH, g_tmpH); GETSYM(h2, g_h2);
    GETSYM(e, g_e);     GETSYM(x1, g_x1);     GETSYM(xn, g_xn);
    GETSYM(xz, g_xz);   GETSYM(xm2, g_xm2);   GETSYM(dbc, g_dbc);
    GETSYM(del, g_del); GETSYM(y, g_y);       GETSYM(mo, g_mo);
    GETSYM(gl, g_gl);   GETSYM(xf, g_xf);
    GETSYM(rm, g_rm);   GETSYM(rs, g_rs);     GETSYM(rm2, g_rm2); GETSYM(rs2, g_rs2);
    GETSYM(fid, g_fid); GETSYM(stats, g_stats);

    float* sum1 = stats + ST_SUM1;
    float* sq1  = stats + ST_SQ1;
    float* sum2 = stats + ST_SUM2;
    float* sq2  = stats + ST_SQ2;
    float* sum3 = stats + ST_SUM3;
    float* sq3  = stats + ST_SQ3;

    static cudaStream_t s1 = 0;
    static cudaEvent_t evFork = 0, evZ = 0, evJoin = 0;
    static int smemSet = 0;
    if (!s1) {
        cudaStreamCreateWithFlags(&s1, cudaStreamNonBlocking);
        cudaEventCreateWithFlags(&evFork, cudaEventDisableTiming);
        cudaEventCreateWithFlags(&evZ, cudaEventDisableTiming);
        cudaEventCreateWithFlags(&evJoin, cudaEventDisableTiming);
    }
    if (!smemSet) {
        cudaFuncSetAttribute(gemm_tc<0>, cudaFuncAttributeMaxDynamicSharedMemorySize, GEMM_DSMEM);
        cudaFuncSetAttribute(gemm_tc<1>, cudaFuncAttributeMaxDynamicSharedMemorySize, GEMM_DSMEM);
        smemSet = 1;
    }

    const int T = 256;
    dim3 gHID((Nq*HIDq + T-1)/T), gDI((Nq*DIq + T-1)/T);

    cudaMemsetAsync(stats, 0, ST_TOTAL*sizeof(float));

    // 1) squeeze GEMM + BN+SiLU
    gemm_tc<0><<<dim3(2, Nq/128), 256, GEMM_DSMEM>>>(x, Dq, sq_w, h0, HIDq, HIDq, Dq, 0);
    bn_stats<<<dim3(256,1), T>>>(h0, Nq, HIDq, sum1, sq1);
    bn_silu<<<gHID, T>>>(h0, h0, sum1, sq1, sq_bn_g, sq_bn_b, Nq, HIDq);

    // 2) dwconv K=5 + BN+SiLU
    dwconv5<<<gHID, T>>>(h0, dw_w, tmpH);
    bn_stats<<<dim3(256,1), T>>>(tmpH, Nq, HIDq, sum2, sq2);
    bn_silu<<<gHID, T>>>(tmpH, h2, sum2, sq2, dw_bn_g, dw_bn_b, Nq, HIDq);

    // 3) excite GEMM + fused bn_add + LN
    gemm_tc<0><<<dim3(6, Nq/128), 256, GEMM_DSMEM>>>(h2, HIDq, ex_w, e, Dq, Dq, HIDq, 0);
    bn_stats<<<dim3(256,3), T>>>(e, Nq, Dq, sum3, sq3);
    bn_add_ln<<<Nq, T>>>(e, x, sum3, sq3, ex_bn_g, ex_bn_b, mnorm_g, mnorm_b,
                         x1, xn, rm, rs);

    // fork: side stream computes z-half of in_proj (needed by scan), then
    // feat_attr and the gate GEMM (needed by combine)
    cudaEventRecord(evFork, 0);
    cudaStreamWaitEvent(s1, evFork, 0);
    gemm_tc<0><<<dim3(12, Nq/128), 256, GEMM_DSMEM, s1>>>(
        xn, Dq, in_proj_w + (size_t)DIq*Dq, xz + DIq, DIq, 2*DIq, Dq, 0);
    cudaEventRecord(evZ, s1);
    attr_max<<<dim3(Bq,3), T, 0, s1>>>(x1, rm, rs, attr_g, attr_b, out);
    gemm_tc<0><<<dim3(6, Nq/128), 256, GEMM_DSMEM, s1>>>(xn, Dq, gate_w, gl, Dq, Dq, Dq, 0);
    cudaEventRecord(evJoin, s1);

    // 5) main: xm-half of in_proj
    gemm_tc<0><<<dim3(12, Nq/128), 256, GEMM_DSMEM>>>(
        xn, Dq, in_proj_w, xz, DIq, 2*DIq, Dq, 0);

    // 6) causal conv + silu (reads xm half only)
    conv_causal_silu<<<gDI, T>>>(xz, conv_w, conv_b, xm2);

    // 7) x_proj; dt_proj (+softplus epilogue)
    gemm_tc<0><<<dim3(1, Nq/128), 256, GEMM_DSMEM>>>(xm2, DIq, xproj_w, dbc, 80, 80, DIq, 0);
    gemm_tc<1><<<dim3(12, Nq/128), 256, GEMM_DSMEM>>>(dbc, 80, dtproj_w, del, DIq, DIq, DTRq, dtproj_b);

    // 8) selective scan (needs z-half)
    cudaStreamWaitEvent(0, evZ, 0);
    scan_k<<<dim3(DIq/128, Bq), 128>>>(del, xm2, dbc, xz, A_log, D_param, y);

    // 9) out_proj; join gate; fused combine + LN stats
    gemm_tc<0><<<dim3(6, Nq/128), 256, GEMM_DSMEM>>>(y, DIq, out_proj_w, mo, Dq, Dq, DIq, 0);
    cudaStreamWaitEvent(0, evJoin, 0);
    combine_ln<<<Nq, T>>>(x, x1, mo, gl, gate_b, xf, rm2, rs2);

    // 10) feat_id + feat_id_bn
    feat_id_k<<<dim3(Bq,3), T>>>(xf, rm2, rs2, idn_g, idn_b, fid, out + Bq*Dq);
    feat_bn<<<3, T>>>(fid, idbn_g, idbn_b, out + 2*Bq*Dq);
}

// round 10
// speedup vs baseline: 2.1498x; 1.0529x over previous
#include <cuda_runtime.h>
#include <math.h>
#include <stdint.h>

#define Bq    32
#define Lq    512
#define Dq    768
#define HIDq  192
#define DIq   1536
#define DSq   16
#define DTRq  48
#define Nq    (Bq*Lq)        // 16384
#define EPSq  1e-5f

// ---------------- scratch ----------------
__device__ __align__(256) float g_h0  [Nq*HIDq];
__device__ __align__(256) float g_tmpH[Nq*HIDq];
__device__ __align__(256) float g_h2  [Nq*HIDq];
__device__ __align__(256) float g_e   [Nq*Dq];
__device__ __align__(256) float g_x1  [Nq*Dq];
__device__ __align__(256) float g_xn  [Nq*Dq];
__device__ __align__(256) float g_xz  [Nq*2*DIq];
__device__ __align__(256) float g_xm2 [Nq*DIq];
__device__ __align__(256) float g_dbc [Nq*80];
__device__ __align__(256) float g_del [Nq*DIq];
__device__ __align__(256) float g_y   [Nq*DIq];
__device__ __align__(256) float g_mo  [Nq*Dq];
__device__ __align__(256) float g_gl  [Nq*Dq];
__device__ __align__(256) float g_xf  [Nq*Dq];
__device__ __align__(256) float g_rm  [Nq];
__device__ __align__(256) float g_rs  [Nq];
__device__ __align__(256) float g_rm2 [Nq];
__device__ __align__(256) float g_rs2 [Nq];
__device__ __align__(256) float g_fid [Bq*Dq];
__device__ __align__(256) float g_xr  [Nq*Dq];     // tf32-rounded x
// tf32-rounded weights, concatenated
#define W_SQ   0
#define W_EX   (W_SQ  + HIDq*Dq)        // 147456
#define W_INP  (W_EX  + Dq*HIDq)        // +147456
#define W_XP   (W_INP + 2*DIq*Dq)       // +2359296
#define W_DT   (W_XP  + 80*DIq)         // +122880
#define W_OUT  (W_DT  + DIq*DTRq)       // +73728
#define W_GATE (W_OUT + Dq*DIq)         // +1179648
#define W_TOT  (W_GATE + Dq*Dq)         // +589824
__device__ __align__(256) float g_wr[W_TOT];
#define ST_SUM1   0
#define ST_SQ1    (ST_SUM1+192)
#define ST_SUM2   (ST_SQ1+192)
#define ST_SQ2    (ST_SUM2+192)
#define ST_SUM3   (ST_SQ2+192)
#define ST_SQ3    (ST_SUM3+768)
#define ST_TOTAL  (ST_SQ3+768)
__device__ __align__(256) float g_stats[ST_TOTAL];

// ================= helpers =================
__device__ __forceinline__ uint32_t f2tf(float f) {
    uint32_t u;
    asm("cvt.rna.tf32.f32 %0, %1;" : "=r"(u) : "f"(f));
    return u;
}
__device__ __forceinline__ float f2tf_f(float f) { return __uint_as_float(f2tf(f)); }

__device__ __forceinline__ void mma_tf32(float* d, const uint32_t* a, const uint32_t* b) {
    asm volatile(
        "mma.sync.aligned.m16n8k8.row.col.f32.tf32.tf32.f32 "
        "{%0,%1,%2,%3}, {%4,%5,%6,%7}, {%8,%9}, {%0,%1,%2,%3};"
        : "+f"(d[0]), "+f"(d[1]), "+f"(d[2]), "+f"(d[3])
        : "r"(a[0]), "r"(a[1]), "r"(a[2]), "r"(a[3]), "r"(b[0]), "r"(b[1]));
}

__device__ __forceinline__ uint32_t smem_u32(const void* p) {
    uint32_t a;
    asm("{ .reg .u64 t; cvta.to.shared.u64 t, %1; cvt.u32.u64 %0, t; }" : "=r"(a) : "l"(p));
    return a;
}
#define CP_ASYNC(dst, src, sz) \
    asm volatile("cp.async.cg.shared.global [%0], [%1], 16, %2;" \
                 :: "r"(dst), "l"(src), "r"(sz) : "memory")
#define CP_COMMIT() asm volatile("cp.async.commit_group;" ::: "memory")
#define CP_WAIT(n)  asm volatile("cp.async.wait_group %0;" :: "n"(n) : "memory")

// ================= TF32 GEMM: cp.async staged, 2 CTAs/SM =================
// C[M,Nc] = A[M,K](lda) @ W[Nc,K]^T, C row stride ldc. Inputs PRE-ROUNDED to tf32.
// MODE 0: plain store. MODE 1: softplus(v+p0[c]). MODE 2: tf32-rounded store.
#define SA 36
#define TILE_U (128*SA)
#define GEMM_DSMEM (2*2*TILE_U*4)

template<int MODE>
__global__ void __launch_bounds__(256, 2) gemm_tc(
    const float* __restrict__ A, int lda,
    const float* __restrict__ W,
    float* __restrict__ C, int Nc, int ldc, int K,
    const float* __restrict__ p0)
{
    extern __shared__ uint32_t dsm[];
    const uint32_t sbase = smem_u32(dsm);

    const int bm = blockIdx.y * 128;
    const int bn = blockIdx.x * 128;
    const int t  = threadIdx.x;
    const int wid  = t >> 5;
    const int lane = t & 31;
    const int qr = lane >> 2;
    const int qc = lane & 3;
    const int warp_m = wid & 3;
    const int warp_n = wid >> 2;

    const int r0t = t >> 3;            // 0..31
    const int c4  = (t & 7) * 4;       // 0..28

    const float* aRow[4];
    const float* bRow[4];
    int bOk[4];
    uint32_t dstOff[4];
    #pragma unroll
    for (int i = 0; i < 4; i++) {
        int r = r0t + i*32;
        aRow[i] = A + (size_t)(bm + r)*lda;
        int j = bn + r;
        bOk[i] = (j < Nc);
        bRow[i] = W + (size_t)(bOk[i] ? j : 0)*K;
        dstOff[i] = (uint32_t)(r*SA + c4) * 4u;
    }

    float acc[2][8][4];
    #pragma unroll
    for (int mt = 0; mt < 2; mt++)
        #pragma unroll
        for (int nt = 0; nt < 8; nt++)
            #pragma unroll
            for (int q = 0; q < 4; q++) acc[mt][nt][q] = 0.f;

    const int NC = (K + 31) / 32;

    // prologue: issue chunk 0 into stage 0
    {
        int k = c4;
        int szA = (k < K) ? 16 : 0;
        #pragma unroll
        for (int i = 0; i < 4; i++)
            CP_ASYNC(sbase + dstOff[i], aRow[i] + k, szA);
        #pragma unroll
        for (int i = 0; i < 4; i++) {
            int szB = (bOk[i] && k < K) ? 16 : 0;
            CP_ASYNC(sbase + (uint32_t)TILE_U*4 + dstOff[i], bRow[i] + k, szB);
        }
        CP_COMMIT();
    }

    for (int ch = 0; ch < NC; ch++) {
        const int buf = ch & 1;
        // issue next chunk into other stage
        if (ch + 1 < NC) {
            const int k = (ch + 1)*32 + c4;
            uint32_t base = sbase + (uint32_t)(buf ^ 1) * 2u * TILE_U * 4u;
            int szA = (k < K) ? 16 : 0;
            #pragma unroll
            for (int i = 0; i < 4; i++)
                CP_ASYNC(base + dstOff[i], aRow[i] + k, szA);
            #pragma unroll
            for (int i = 0; i < 4; i++) {
                int szB = (bOk[i] && k < K) ? 16 : 0;
                CP_ASYNC(base + (uint32_t)TILE_U*4 + dstOff[i], bRow[i] + k, szB);
            }
            CP_COMMIT();
            CP_WAIT(1);
        } else {
            CP_WAIT(0);
        }
        __syncthreads();

        const uint32_t* As = dsm + (size_t)buf * 2 * TILE_U;
        const uint32_t* Bs = As + TILE_U;
        #pragma unroll
        for (int ks = 0; ks < 4; ks++) {
            const int k0 = ks * 8;
            uint32_t afr[2][4];
            #pragma unroll
            for (int mt = 0; mt < 2; mt++) {
                int r0 = warp_m*32 + mt*16 + qr;
                afr[mt][0] = As[r0*SA + k0 + qc];
                afr[mt][1] = As[(r0+8)*SA + k0 + qc];
                afr[mt][2] = As[r0*SA + k0 + qc + 4];
                afr[mt][3] = As[(r0+8)*SA + k0 + qc + 4];
            }
            uint32_t bfr[8][2];
            #pragma unroll
            for (int nt = 0; nt < 8; nt++) {
                int n = warp_n*64 + nt*8 + qr;
                bfr[nt][0] = Bs[n*SA + k0 + qc];
                bfr[nt][1] = Bs[n*SA + k0 + qc + 4];
            }
            #pragma unroll
            for (int mt = 0; mt < 2; mt++)
                #pragma unroll
                for (int nt = 0; nt < 8; nt++)
                    mma_tf32(acc[mt][nt], afr[mt], bfr[nt]);
        }
        __syncthreads();   // reads done before next iter overwrites this stage
    }

    if (MODE == 0 || MODE == 2) {
        #pragma unroll
        for (int mt = 0; mt < 2; mt++) {
            int r0 = bm + warp_m*32 + mt*16 + qr;
            #pragma unroll
            for (int nt = 0; nt < 8; nt++) {
                int c = bn + warp_n*64 + nt*8 + qc*2;
                if (c < Nc) {
                    float v0 = acc[mt][nt][0], v1 = acc[mt][nt][1];
                    float v2 = acc[mt][nt][2], v3 = acc[mt][nt][3];
                    if (MODE == 2) { v0 = f2tf_f(v0); v1 = f2tf_f(v1); v2 = f2tf_f(v2); v3 = f2tf_f(v3); }
                    *(float2*)&C[(size_t)r0*ldc + c]     = make_float2(v0, v1);
                    *(float2*)&C[(size_t)(r0+8)*ldc + c] = make_float2(v2, v3);
                }
            }
        }
    } else {
        #pragma unroll
        for (int mt = 0; mt < 2; mt++) {
            int r0 = bm + warp_m*32 + mt*16 + qr;
            #pragma unroll
            for (int nt = 0; nt < 8; nt++) {
                int c = bn + warp_n*64 + nt*8 + qc*2;
                if (c < Nc) {
                    float b0 = p0[c], b1 = p0[c+1];
                    float v;
                    v = acc[mt][nt][0] + b0; v = (v > 20.f) ? v : log1pf(__expf(v));
                    C[(size_t)r0*ldc + c] = v;
                    v = acc[mt][nt][1] + b1; v = (v > 20.f) ? v : log1pf(__expf(v));
                    C[(size_t)r0*ldc + c + 1] = v;
                    v = acc[mt][nt][2] + b0; v = (v > 20.f) ? v : log1pf(__expf(v));
                    C[(size_t)(r0+8)*ldc + c] = v;
                    v = acc[mt][nt][3] + b1; v = (v > 20.f) ? v : log1pf(__expf(v));
                    C[(size_t)(r0+8)*ldc + c + 1] = v;
                }
            }
        }
    }
}

// ---------------- tf32 pre-round (vectorized) ----------------
__global__ void round_tf32(const float* __restrict__ X, float* __restrict__ Y, int n4)
{
    int i = blockIdx.x * blockDim.x + threadIdx.x;
    if (i >= n4) return;
    float4 v = ((const float4*)X)[i];
    v.x = f2tf_f(v.x); v.y = f2tf_f(v.y); v.z = f2tf_f(v.z); v.w = f2tf_f(v.w);
    ((float4*)Y)[i] = v;
}

// ---------------- BatchNorm stats ----------------
__global__ void bn_stats(const float* __restrict__ X, int M, int C,
                         float* __restrict__ sum, float* __restrict__ sq)
{
    int c = blockIdx.y * blockDim.x + threadIdx.x;
    if (c >= C) return;
    int rows = M / gridDim.x;
    int r0 = blockIdx.x * rows;
    float s = 0.f, ss = 0.f;
    for (int r = r0; r < r0 + rows; r++) {
        float v = X[(size_t)r*C + c];
        s += v; ss += v*v;
    }
    atomicAdd(&sum[c], s);
    atomicAdd(&sq[c],  ss);
}

// output tf32-rounded (feeds GEMM directly or via dwconv+BN, harmless)
__global__ void bn_silu(const float* __restrict__ X, float* __restrict__ Y,
                        const float* __restrict__ sum, const float* __restrict__ sq,
                        const float* __restrict__ g, const float* __restrict__ b,
                        int M, int C)
{
    int idx = blockIdx.x * blockDim.x + threadIdx.x;
    if (idx >= M*C) return;
    int c = idx % C;
    float mean = sum[c] / (float)M;
    float var  = sq[c] / (float)M - mean*mean;
    float v = (X[idx] - mean) * rsqrtf(var + EPSq) * g[c] + b[c];
    Y[idx] = f2tf_f(v / (1.f + __expf(-v)));
}

// ---------------- depthwise conv K=5 ----------------
__global__ void dwconv5(const float* __restrict__ X, const float* __restrict__ w,
                        float* __restrict__ Y)
{
    int idx = blockIdx.x * blockDim.x + threadIdx.x;
    if (idx >= Nq*HIDq) return;
    int c  = idx % HIDq;
    int l  = (idx / HIDq) % Lq;
    int bb = idx / (HIDq*Lq);
    const float* xb = X + (size_t)bb*Lq*HIDq;
    float acc = 0.f;
    #pragma unroll
    for (int k = 0; k < 5; k++) {
        int ls = l - 2 + k;
        if (ls >= 0 && ls < Lq) acc += xb[(size_t)ls*HIDq + c] * w[c*5 + k];
    }
    Y[idx] = acc;
}

// ---------------- bn_add + LN, fused (xn store tf32-rounded) ----------------
__global__ void __launch_bounds__(256) bn_add_ln(
    const float* __restrict__ E, const float* __restrict__ X,
    const float* __restrict__ sum3, const float* __restrict__ sq3,
    const float* __restrict__ exg, const float* __restrict__ exb,
    const float* __restrict__ lng, const float* __restrict__ lnb,
    float* __restrict__ X1, float* __restrict__ XN,
    float* __restrict__ rm, float* __restrict__ rs)
{
    const int row = blockIdx.x;
    const int tid = threadIdx.x;
    float vloc[3];
    float s = 0.f, ss = 0.f;
    #pragma unroll
    for (int j = 0; j < 3; j++) {
        int c = tid + j*256;
        float mean = sum3[c] / (float)Nq;
        float var  = sq3[c] / (float)Nq - mean*mean;
        float ga = rsqrtf(var + EPSq) * exg[c];
        float be = exb[c] - mean*ga;
        float v = X[(size_t)row*Dq + c] + E[(size_t)row*Dq + c]*ga + be;
        vloc[j] = v;
        s += v; ss += v*v;
    }
    __shared__ float sh1[8], sh2[8], bcast[2];
    for (int o = 16; o; o >>= 1) {
        s  += __shfl_down_sync(0xffffffffu, s, o);
        ss += __shfl_down_sync(0xffffffffu, ss, o);
    }
    int lane = tid & 31, warp = tid >> 5;
    if (lane == 0) { sh1[warp] = s; sh2[warp] = ss; }
    __syncthreads();
    if (tid == 0) {
        s = 0.f; ss = 0.f;
        #pragma unroll
        for (int wv = 0; wv < 8; wv++) { s += sh1[wv]; ss += sh2[wv]; }
        float m = s / (float)Dq;
        float v = ss / (float)Dq - m*m;
        float r = rsqrtf(v + EPSq);
        bcast[0] = m; bcast[1] = r;
        rm[row] = m; rs[row] = r;
    }
    __syncthreads();
    float m = bcast[0], r = bcast[1];
    #pragma unroll
    for (int j = 0; j < 3; j++) {
        int c = tid + j*256;
        X1[(size_t)row*Dq + c] = vloc[j];
        XN[(size_t)row*Dq + c] = f2tf_f((vloc[j] - m) * r * lng[c] + lnb[c]);
    }
}

// ---------------- combine + LN stats, fused ----------------
__global__ void __launch_bounds__(256) combine_ln(
    const float* __restrict__ X, const float* __restrict__ X1,
    const float* __restrict__ MO, const float* __restrict__ GL,
    const float* __restrict__ gb,
    float* __restrict__ XF, float* __restrict__ rm2, float* __restrict__ rs2)
{
    const int row = blockIdx.x;
    const int tid = threadIdx.x;
    float vloc[3];
    float s = 0.f, ss = 0.f;
    #pragma unroll
    for (int j = 0; j < 3; j++) {
        int c = tid + j*256;
        size_t i = (size_t)row*Dq + c;
        float gate = 1.f / (1.f + __expf(-(GL[i] + gb[c])));
        float v = X1[i] + MO[i]*gate + X[i];
        vloc[j] = v;
        s += v; ss += v*v;
    }
    __shared__ float sh1[8], sh2[8];
    for (int o = 16; o; o >>= 1) {
        s  += __shfl_down_sync(0xffffffffu, s, o);
        ss += __shfl_down_sync(0xffffffffu, ss, o);
    }
    int lane = tid & 31, warp = tid >> 5;
    if (lane == 0) { sh1[warp] = s; sh2[warp] = ss; }
    __syncthreads();
    if (tid == 0) {
        s = 0.f; ss = 0.f;
        #pragma unroll
        for (int wv = 0; wv < 8; wv++) { s += sh1[wv]; ss += sh2[wv]; }
        float m = s / (float)Dq;
        float v = ss / (float)Dq - m*m;
        rm2[row] = m;
        rs2[row] = rsqrtf(v + EPSq);
    }
    #pragma unroll
    for (int j = 0; j < 3; j++) {
        int c = tid + j*256;
        XF[(size_t)row*Dq + c] = vloc[j];
    }
}

// ---------------- causal conv K=4 + bias + silu (tf32-rounded out) ----------------
__global__ void conv_causal_silu(const float* __restrict__ XZ, const float* __restrict__ w,
                                 const float* __restrict__ bias, float* __restrict__ Y)
{
    int idx = blockIdx.x * blockDim.x + threadIdx.x;
    if (idx >= Nq*DIq) return;
    int c  = idx % DIq;
    int l  = (idx / DIq) % Lq;
    int bb = idx / (DIq*Lq);
    float acc = bias[c];
    #pragma unroll
    for (int k = 0; k < 4; k++) {
        int ls = l - 3 + k;
        if (ls >= 0) acc += XZ[(size_t)(bb*Lq + ls)*(2*DIq) + c] * w[c*4 + k];
    }
    Y[idx] = f2tf_f(acc / (1.f + __expf(-acc)));
}

// feat_attr
__global__ void attr_max(const float* __restrict__ X, const float* __restrict__ mean,
                         const float* __restrict__ rstd, const float* __restrict__ g,
                         const float* __restrict__ b, float* __restrict__ out)
{
    int c  = blockIdx.y * blockDim.x + threadIdx.x;
    int bb = blockIdx.x;
    float gm = g[c], gb = b[c];
    float mx = -3.4e38f;
    for (int l = 0; l < Lq; l++) {
        int row = bb*Lq + l;
        float v = (X[(size_t)row*Dq + c] - mean[row]) * rstd[row] * gm + gb;
        mx = fmaxf(mx, v);
    }
    out[bb*Dq + c] = mx;
}

// ---------------- selective scan (y tf32-rounded) ----------------
__global__ void __launch_bounds__(128) scan_k(
    const float* __restrict__ delta, const float* __restrict__ u,
    const float* __restrict__ dbc,   const float* __restrict__ xz,
    const float* __restrict__ A_log, const float* __restrict__ Dp,
    float* __restrict__ y)
{
    __shared__ float Bs[128][DSq];
    __shared__ float Cs[128][DSq];
    const int bb = blockIdx.y;
    const int d  = blockIdx.x * 128 + threadIdx.x;

    float A[DSq], h[DSq];
    bool fast = true;
    #pragma unroll
    for (int s = 0; s < DSq; s++) {
        A[s] = -expf(A_log[d*DSq + s]);
        h[s] = 0.f;
        if (fabsf(A[s] + (float)(s+1)) > 1e-3f * (float)(s+1)) fast = false;
    }
    const float dp = Dp[d];

    for (int c0 = 0; c0 < Lq; c0 += 128) {
        for (int i = threadIdx.x; i < 128*DSq; i += 128) {
            int l = i >> 4, s = i & 15;
            size_t row = (size_t)(bb*Lq + c0 + l);
            Bs[l][s] = dbc[row*80 + DTRq + s];
            Cs[l][s] = dbc[row*80 + DTRq + DSq + s];
        }
        __syncthreads();
        size_t row0 = (size_t)(bb*Lq + c0);
        float dv = delta[row0*DIq + d];
        float uv = u[row0*DIq + d];
        float zv = xz[row0*(2*DIq) + DIq + d];
        if (fast) {
            for (int l = 0; l < 128; l++) {
                float nd = 0.f, nu = 0.f, nz = 0.f;
                if (l < 127) {
                    size_t rn = row0 + l + 1;
                    nd = delta[rn*DIq + d];
                    nu = u[rn*DIq + d];
                    nz = xz[rn*(2*DIq) + DIq + d];
                }
                float du = dv * uv;
                float e1 = __expf(-dv);
                float p = e1;
                float acc = 0.f;
                #pragma unroll
                for (int s = 0; s < DSq; s++) {
                    h[s] = h[s] * p + du * Bs[l][s];
                    acc  = fmaf(h[s], Cs[l][s], acc);
                    p *= e1;
                }
                float sz = zv / (1.f + __expf(-zv));
                y[(row0 + l)*DIq + d] = f2tf_f((acc + uv*dp) * sz);
                dv = nd; uv = nu; zv = nz;
            }
        } else {
            for (int l = 0; l < 128; l++) {
                float nd = 0.f, nu = 0.f, nz = 0.f;
                if (l < 127) {
                    size_t rn = row0 + l + 1;
                    nd = delta[rn*DIq + d];
                    nu = u[rn*DIq + d];
                    nz = xz[rn*(2*DIq) + DIq + d];
                }
                float du = dv * uv;
                float acc = 0.f;
                #pragma unroll
                for (int s = 0; s < DSq; s++) {
                    h[s] = h[s] * __expf(dv * A[s]) + du * Bs[l][s];
                    acc  = fmaf(h[s], Cs[l][s], acc);
                }
                float sz = zv / (1.f + __expf(-zv));
                y[(row0 + l)*DIq + d] = f2tf_f((acc + uv*dp) * sz);
                dv = nd; uv = nu; zv = nz;
            }
        }
        __syncthreads();
    }
}

// feat_id
__global__ void feat_id_k(const float* __restrict__ X, const float* __restrict__ mean,
                          const float* __restrict__ rstd, const float* __restrict__ g,
                          const float* __restrict__ b, float* __restrict__ fid,
                          float* __restrict__ out)
{
    int c  = blockIdx.y * blockDim.x + threadIdx.x;
    int bb = blockIdx.x;
    float gm = g[c], gb = b[c];
    float s = 0.f;
    for (int l = 0; l < Lq; l++) {
        int row = bb*Lq + l;
        s += (X[(size_t)row*Dq + c] - mean[row]) * rstd[row] * gm + gb;
    }
    float v = s / (float)Lq;
    fid[bb*Dq + c] = v;
    out[bb*Dq + c] = v;
}

__global__ void feat_bn(const float* __restrict__ fid, const float* __restrict__ g,
                        const float* __restrict__ b, float* __restrict__ out)
{
    int c = blockIdx.x * blockDim.x + threadIdx.x;
    if (c >= Dq) return;
    float s = 0.f, ss = 0.f;
    for (int bb = 0; bb < Bq; bb++) {
        float v = fid[bb*Dq + c]; s += v; ss += v*v;
    }
    float m = s / (float)Bq;
    float var = ss / (float)Bq - m*m;
    float rs = rsqrtf(var + EPSq);
    for (int bb = 0; bb < Bq; bb++)
        out[bb*Dq + c] = (fid[bb*Dq + c] - m) * rs * g[c] + b[c];
}

// ---------------- host ----------------
#define GETSYM(p, s) { void* _t; cudaGetSymbolAddress(&_t, s); p = (float*)_t; }

extern "C" void kernel_launch(void* const* d_in, const int* in_sizes, int n_in,
                              void* d_out, int out_size)
{
    const float* x        = (const float*)d_in[0];
    const float* sq_w     = (const float*)d_in[1];
    const float* sq_bn_g  = (const float*)d_in[2];
    const float* sq_bn_b  = (const float*)d_in[3];
    const float* dw_w     = (const float*)d_in[4];
    const float* dw_bn_g  = (const float*)d_in[5];
    const float* dw_bn_b  = (const float*)d_in[6];
    const float* ex_w     = (const float*)d_in[7];
    const float* ex_bn_g  = (const float*)d_in[8];
    const float* ex_bn_b  = (const float*)d_in[9];
    const float* attr_g   = (const float*)d_in[10];
    const float* attr_b   = (const float*)d_in[11];
    const float* mnorm_g  = (const float*)d_in[12];
    const float* mnorm_b  = (const float*)d_in[13];
    const float* in_proj_w= (const float*)d_in[14];
    const float* conv_w   = (const float*)d_in[15];
    const float* conv_b   = (const float*)d_in[16];
    const float* xproj_w  = (const float*)d_in[17];
    const float* dtproj_w = (const float*)d_in[18];
    const float* dtproj_b = (const float*)d_in[19];
    const float* A_log    = (const float*)d_in[20];
    const float* D_param  = (const float*)d_in[21];
    const float* out_proj_w = (const float*)d_in[22];
    const float* gate_w   = (const float*)d_in[23];
    const float* gate_b   = (const float*)d_in[24];
    const float* idn_g    = (const float*)d_in[25];
    const float* idn_b    = (const float*)d_in[26];
    const float* idbn_g   = (const float*)d_in[27];
    const float* idbn_b   = (const float*)d_in[28];
    float* out = (float*)d_out;

    float *h0,*tmpH,*h2,*e,*x1,*xn,*xz,*xm2,*dbc,*del,*y,*mo,*gl,*xf;
    float *rm,*rs,*rm2,*rs2,*fid,*stats,*xr,*wr;
    GETSYM(h0, g_h0);   GETSYM(tmpH, g_tmpH); GETSYM(h2, g_h2);
    GETSYM(e, g_e);     GETSYM(x1, g_x1);     GETSYM(xn, g_xn);
    GETSYM(xz, g_xz);   GETSYM(xm2, g_xm2);   GETSYM(dbc, g_dbc);
    GETSYM(del, g_del); GETSYM(y, g_y);       GETSYM(mo, g_mo);
    GETSYM(gl, g_gl);   GETSYM(xf, g_xf);
    GETSYM(rm, g_rm);   GETSYM(rs, g_rs);     GETSYM(rm2, g_rm2); GETSYM(rs2, g_rs2);
    GETSYM(fid, g_fid); GETSYM(stats, g_stats);
    GETSYM(xr, g_xr);   GETSYM(wr, g_wr);

    float* sum1 = stats + ST_SUM1;
    float* sq1  = stats + ST_SQ1;
    float* sum2 = stats + ST_SUM2;
    float* sq2  = stats + ST_SQ2;
    float* sum3 = stats + ST_SUM3;
    float* sq3  = stats + ST_SQ3;

    static cudaStream_t s1 = 0;
    static cudaEvent_t evFork = 0, evZ = 0, evJoin = 0;
    static int smemSet = 0;
    if (!s1) {
        cudaStreamCreateWithFlags(&s1, cudaStreamNonBlocking);
        cudaEventCreateWithFlags(&evFork, cudaEventDisableTiming);
        cudaEventCreateWithFlags(&evZ, cudaEventDisableTiming);
        cudaEventCreateWithFlags(&evJoin, cudaEventDisableTiming);
    }
    if (!smemSet) {
        cudaFuncSetAttribute(gemm_tc<0>, cudaFuncAttributeMaxDynamicSharedMemorySize, GEMM_DSMEM);
        cudaFuncSetAttribute(gemm_tc<1>, cudaFuncAttributeMaxDynamicSharedMemorySize, GEMM_DSMEM);
        cudaFuncSetAttribute(gemm_tc<2>, cudaFuncAttributeMaxDynamicSharedMemorySize, GEMM_DSMEM);
        smemSet = 1;
    }

    const int T = 256;
    dim3 gHID((Nq*HIDq + T-1)/T), gDI((Nq*DIq + T-1)/T);

    cudaMemsetAsync(stats, 0, ST_TOTAL*sizeof(float));

    // 0) pre-round x + all weights to tf32 (RNA)
    round_tf32<<<(Nq*Dq/4 + 255)/256, 256>>>(x, xr, Nq*Dq/4);
    round_tf32<<<(HIDq*Dq/4 + 255)/256, 256>>>(sq_w,     wr + W_SQ,  HIDq*Dq/4);
    round_tf32<<<(Dq*HIDq/4 + 255)/256, 256>>>(ex_w,     wr + W_EX,  Dq*HIDq/4);
    round_tf32<<<(2*DIq*Dq/4 + 255)/256, 256>>>(in_proj_w, wr + W_INP, 2*DIq*Dq/4);
    round_tf32<<<(80*DIq/4 + 255)/256, 256>>>(xproj_w,  wr + W_XP,  80*DIq/4);
    round_tf32<<<(DIq*DTRq/4 + 255)/256, 256>>>(dtproj_w, wr + W_DT, DIq*DTRq/4);
    round_tf32<<<(Dq*DIq/4 + 255)/256, 256>>>(out_proj_w, wr + W_OUT, Dq*DIq/4);
    round_tf32<<<(Dq*Dq/4 + 255)/256, 256>>>(gate_w,   wr + W_GATE, Dq*Dq/4);

    // 1) squeeze GEMM + BN+SiLU
    gemm_tc<0><<<dim3(2, Nq/128), 256, GEMM_DSMEM>>>(xr, Dq, wr + W_SQ, h0, HIDq, HIDq, Dq, 0);
    bn_stats<<<dim3(256,1), T>>>(h0, Nq, HIDq, sum1, sq1);
    bn_silu<<<gHID, T>>>(h0, h0, sum1, sq1, sq_bn_g, sq_bn_b, Nq, HIDq);

    // 2) dwconv K=5 + BN+SiLU
    dwconv5<<<gHID, T>>>(h0, dw_w, tmpH);
    bn_stats<<<dim3(256,1), T>>>(tmpH, Nq, HIDq, sum2, sq2);
    bn_silu<<<gHID, T>>>(tmpH, h2, sum2, sq2, dw_bn_g, dw_bn_b, Nq, HIDq);

    // 3) excite GEMM + fused bn_add + LN
    gemm_tc<0><<<dim3(6, Nq/128), 256, GEMM_DSMEM>>>(h2, HIDq, wr + W_EX, e, Dq, Dq, HIDq, 0);
    bn_stats<<<dim3(256,3), T>>>(e, Nq, Dq, sum3, sq3);
    bn_add_ln<<<Nq, T>>>(e, x, sum3, sq3, ex_bn_g, ex_bn_b, mnorm_g, mnorm_b,
                         x1, xn, rm, rs);

    // fork: side stream computes z-half of in_proj, feat_attr, gate GEMM
    cudaEventRecord(evFork, 0);
    cudaStreamWaitEvent(s1, evFork, 0);
    gemm_tc<0><<<dim3(12, Nq/128), 256, GEMM_DSMEM, s1>>>(
        xn, Dq, wr + W_INP + (size_t)DIq*Dq, xz + DIq, DIq, 2*DIq, Dq, 0);
    cudaEventRecord(evZ, s1);
    attr_max<<<dim3(Bq,3), T, 0, s1>>>(x1, rm, rs, attr_g, attr_b, out);
    gemm_tc<0><<<dim3(6, Nq/128), 256, GEMM_DSMEM, s1>>>(xn, Dq, wr + W_GATE, gl, Dq, Dq, Dq, 0);
    cudaEventRecord(evJoin, s1);

    // 5) main: xm-half of in_proj
    gemm_tc<0><<<dim3(12, Nq/128), 256, GEMM_DSMEM>>>(
        xn, Dq, wr + W_INP, xz, DIq, 2*DIq, Dq, 0);

    // 6) causal conv + silu
    conv_causal_silu<<<gDI, T>>>(xz, conv_w, conv_b, xm2);

    // 7) x_proj (rounded store for dtproj); dt_proj (+softplus epilogue)
    gemm_tc<2><<<dim3(1, Nq/128), 256, GEMM_DSMEM>>>(xm2, DIq, wr + W_XP, dbc, 80, 80, DIq, 0);
    gemm_tc<1><<<dim3(12, Nq/128), 256, GEMM_DSMEM>>>(dbc, 80, wr + W_DT, del, DIq, DIq, DTRq, dtproj_b);

    // 8) selective scan (needs z-half)
    cudaStreamWaitEvent(0, evZ, 0);
    scan_k<<<dim3(DIq/128, Bq), 128>>>(del, xm2, dbc, xz, A_log, D_param, y);

    // 9) out_proj; join gate; fused combine + LN stats
    gemm_tc<0><<<dim3(6, Nq/128), 256, GEMM_DSMEM>>>(y, DIq, wr + W_OUT, mo, Dq, Dq, DIq, 0);
    cudaStreamWaitEvent(0, evJoin, 0);
    combine_ln<<<Nq, T>>>(x, x1, mo, gl, gate_b, xf, rm2, rs2);

    // 10) feat_id + feat_id_bn
    feat_id_k<<<dim3(Bq,3), T>>>(xf, rm2, rs2, idn_g, idn_b, fid, out + Bq*Dq);
    feat_bn<<<3, T>>>(fid, idbn_g, idbn_b, out + 2*Bq*Dq);
}